// round 1
// baseline (speedup 1.0000x reference)
#include <cuda_runtime.h>
#include <math.h>

// Problem constants (fixed by the dataset)
#define N_NODES 100000
#define IN_F    256     // input features
#define HD      256     // H*D
#define NH      4       // heads
#define DH      64      // dim per head
#define NEG_SLOPE 0.2f

// ---------------- scratch (device globals; no allocation allowed) ----------
__device__ float g_feat_src[(size_t)N_NODES * HD];   // 102.4 MB
__device__ float g_el[N_NODES * NH];
__device__ float g_er[N_NODES * NH];

// ---------------- Kernel 1: C[M,256] = A[M,256] @ W[256,256]^T -------------
#define BM 128
#define BN 128
#define BK 32
#define PAD 4

__global__ __launch_bounds__(256, 2)
void gemm_kernel(const float* __restrict__ A, const float* __restrict__ W, int M)
{
    __shared__ float As[BK][BM + PAD];
    __shared__ float Bs[BK][BN + PAD];

    const int tid = threadIdx.x;          // 256 threads
    const int tx = tid & 15;              // 0..15
    const int ty = tid >> 4;              // 0..15
    const int row0 = blockIdx.y * BM;
    const int col0 = blockIdx.x * BN;

    float acc[8][8];
    #pragma unroll
    for (int r = 0; r < 8; r++)
        #pragma unroll
        for (int c = 0; c < 8; c++) acc[r][c] = 0.f;

    for (int k0 = 0; k0 < IN_F; k0 += BK) {
        // Load A tile (BM x BK) transposed into As[k][m]
        #pragma unroll
        for (int i = 0; i < 4; i++) {
            int idx = tid + i * 256;          // 0..1023
            int m  = idx >> 3;                // 0..127
            int k4 = (idx & 7) * 4;           // 0,4,...,28
            int gr = row0 + m;
            float4 v = make_float4(0.f, 0.f, 0.f, 0.f);
            if (gr < M)
                v = *reinterpret_cast<const float4*>(A + (size_t)gr * IN_F + k0 + k4);
            As[k4 + 0][m] = v.x; As[k4 + 1][m] = v.y;
            As[k4 + 2][m] = v.z; As[k4 + 3][m] = v.w;
        }
        // Load W tile (BN x BK) transposed into Bs[k][n]  (always in-bounds: HD=256)
        #pragma unroll
        for (int i = 0; i < 4; i++) {
            int idx = tid + i * 256;
            int n  = idx >> 3;
            int k4 = (idx & 7) * 4;
            float4 v = *reinterpret_cast<const float4*>(W + (size_t)(col0 + n) * IN_F + k0 + k4);
            Bs[k4 + 0][n] = v.x; Bs[k4 + 1][n] = v.y;
            Bs[k4 + 2][n] = v.z; Bs[k4 + 3][n] = v.w;
        }
        __syncthreads();

        #pragma unroll
        for (int k = 0; k < BK; k++) {
            float a[8], b[8];
            #pragma unroll
            for (int r = 0; r < 8; r++) a[r] = As[k][ty * 8 + r];
            #pragma unroll
            for (int c = 0; c < 8; c++) b[c] = Bs[k][tx * 8 + c];
            #pragma unroll
            for (int r = 0; r < 8; r++)
                #pragma unroll
                for (int c = 0; c < 8; c++) acc[r][c] = fmaf(a[r], b[c], acc[r][c]);
        }
        __syncthreads();
    }

    #pragma unroll
    for (int r = 0; r < 8; r++) {
        int gr = row0 + ty * 8 + r;
        if (gr < M) {
            float* cp = g_feat_src + (size_t)gr * HD + col0 + tx * 8;
            #pragma unroll
            for (int c = 0; c < 8; c += 4) {
                float4 v = make_float4(acc[r][c], acc[r][c + 1], acc[r][c + 2], acc[r][c + 3]);
                *reinterpret_cast<float4*>(cp + c) = v;
            }
        }
    }
}

// ---------------- Kernel 2: el/er = <feat_src[n,h,:], attn_{l,r}[h,:]> -----
__global__ void el_er_kernel(const float* __restrict__ attn_l,
                             const float* __restrict__ attn_r, int M)
{
    int wid  = (blockIdx.x * blockDim.x + threadIdx.x) >> 5;
    int lane = threadIdx.x & 31;
    if (wid >= M * NH) return;
    int n = wid >> 2;
    int h = wid & 3;

    const float* p = g_feat_src + (size_t)n * HD + h * DH;
    float v0 = p[lane];
    float v1 = p[lane + 32];
    float al0 = attn_l[h * DH + lane],      ar0 = attn_r[h * DH + lane];
    float al1 = attn_l[h * DH + lane + 32], ar1 = attn_r[h * DH + lane + 32];
    float l = v0 * al0 + v1 * al1;
    float r = v0 * ar0 + v1 * ar1;
    #pragma unroll
    for (int o = 16; o; o >>= 1) {
        l += __shfl_xor_sync(0xffffffffu, l, o);
        r += __shfl_xor_sync(0xffffffffu, r, o);
    }
    if (lane == 0) { g_el[wid] = l; g_er[wid] = r; }
}

// ---------------- Kernel 3: edge softmax + multi-head SpMM -----------------
// One warp per (dst node, head). deg is 16 for this dataset (<=32 assumed).
__global__ void agg_kernel(const int* __restrict__ row_ptr,
                           const int* __restrict__ col_ind,
                           float* __restrict__ out, int M)
{
    int wid  = (blockIdx.x * blockDim.x + threadIdx.x) >> 5;
    int lane = threadIdx.x & 31;
    if (wid >= M * NH) return;
    int n = wid >> 2;
    int h = wid & 3;

    int lo  = row_ptr[n];
    int hi  = row_ptr[n + 1];
    int deg = hi - lo;

    float* op = out + (size_t)n * HD + h * DH;
    if (deg <= 0) {   // not expected for this dataset, but stay defined
        op[lane] = 0.f; op[lane + 32] = 0.f;
        return;
    }

    float eln = g_el[wid];
    float e = -INFINITY;
    int   src = 0;
    if (lane < deg) {
        src = col_ind[lo + lane];
        float x = g_er[src * NH + h] + eln;
        e = (x > 0.f) ? x : NEG_SLOPE * x;
    }
    float m = e;
    #pragma unroll
    for (int o = 16; o; o >>= 1) m = fmaxf(m, __shfl_xor_sync(0xffffffffu, m, o));
    float p = (lane < deg) ? __expf(e - m) : 0.f;
    float s = p;
    #pragma unroll
    for (int o = 16; o; o >>= 1) s += __shfl_xor_sync(0xffffffffu, s, o);
    float inv = 1.f / s;

    float acc0 = 0.f, acc1 = 0.f;
    #pragma unroll 4
    for (int j = 0; j < deg; j++) {
        float a  = __shfl_sync(0xffffffffu, p, j) * inv;
        int   sj = __shfl_sync(0xffffffffu, src, j);
        const float* q = g_feat_src + (size_t)sj * HD + h * DH;
        acc0 = fmaf(a, q[lane],      acc0);
        acc1 = fmaf(a, q[lane + 32], acc1);
    }
    op[lane]      = acc0;
    op[lane + 32] = acc1;
}

// ---------------- launch ---------------------------------------------------
extern "C" void kernel_launch(void* const* d_in, const int* in_sizes, int n_in,
                              void* d_out, int out_size)
{
    const int*   row_ptr = (const int*)  d_in[0];
    const int*   col_ind = (const int*)  d_in[1];
    const float* feat    = (const float*)d_in[2];
    const float* W       = (const float*)d_in[3];
    const float* attn_l  = (const float*)d_in[4];
    const float* attn_r  = (const float*)d_in[5];
    float* out = (float*)d_out;

    int M = in_sizes[0] - 1;   // number of nodes

    // 1) GEMM: feat_src = feat @ W^T
    dim3 g1(HD / BN, (M + BM - 1) / BM);
    gemm_kernel<<<g1, 256>>>(feat, W, M);

    // 2) el / er
    {
        int warps = M * NH;
        int threads = 256;
        int blocks = (warps * 32 + threads - 1) / threads;
        el_er_kernel<<<blocks, threads>>>(attn_l, attn_r, M);
    }

    // 3) edge softmax + aggregate
    {
        int warps = M * NH;
        int threads = 256;
        int blocks = (warps * 32 + threads - 1) / threads;
        agg_kernel<<<blocks, threads>>>(row_ptr, col_ind, out, M);
    }
}

// round 3
// speedup vs baseline: 1.4366x; 1.4366x over previous
#include <cuda_runtime.h>
#include <cuda_bf16.h>
#include <cstdint>
#include <math.h>

// Problem constants (fixed by the dataset)
#define N_NODES 100000
#define IN_F    256
#define HD      256
#define NH      4
#define DH      64
#define NEG_SLOPE 0.2f

// ---------------- scratch (device globals; no allocation allowed) ----------
__device__ float g_feat_src[(size_t)N_NODES * HD];   // 102.4 MB
__device__ float g_el[N_NODES * NH];
__device__ float g_er[N_NODES * NH];
__device__ __nv_bfloat16 g_A_hi[(size_t)N_NODES * IN_F];
__device__ __nv_bfloat16 g_A_lo[(size_t)N_NODES * IN_F];
__device__ __nv_bfloat16 g_W_hi[HD * IN_F];
__device__ __nv_bfloat16 g_W_lo[HD * IN_F];

// ---------------- helpers ---------------------------------------------------
__device__ __forceinline__ uint32_t smem_u32(const void* p) {
    uint32_t a;
    asm("{ .reg .u64 t; cvta.to.shared.u64 t, %1; cvt.u32.u64 %0, t; }"
        : "=r"(a) : "l"(p));
    return a;
}

#define LDSM_X4(r, addr)                                                      \
    asm volatile("ldmatrix.sync.aligned.m8n8.x4.shared.b16 {%0,%1,%2,%3}, [%4];" \
        : "=r"((r)[0]), "=r"((r)[1]), "=r"((r)[2]), "=r"((r)[3]) : "r"(addr))

#define MMA_BF16(d, a, b0, b1)                                                \
    asm volatile("mma.sync.aligned.m16n8k16.row.col.f32.bf16.bf16.f32 "       \
        "{%0,%1,%2,%3}, {%4,%5,%6,%7}, {%8,%9}, {%0,%1,%2,%3};"               \
        : "+f"((d)[0]), "+f"((d)[1]), "+f"((d)[2]), "+f"((d)[3])              \
        : "r"((a)[0]), "r"((a)[1]), "r"((a)[2]), "r"((a)[3]),                 \
          "r"(b0), "r"(b1))

#define CP_ASYNC16(saddr, gptr, sz)                                           \
    asm volatile("cp.async.cg.shared.global [%0], [%1], 16, %2;"              \
        :: "r"(saddr), "l"(gptr), "r"(sz))

// ---------------- Kernel A: fp32 -> bf16 hi/lo split -----------------------
__global__ void convert_kernel(const float* __restrict__ src,
                               __nv_bfloat16* __restrict__ hi,
                               __nv_bfloat16* __restrict__ lo, int n4)
{
    int i = blockIdx.x * blockDim.x + threadIdx.x;
    if (i >= n4) return;
    float4 v = reinterpret_cast<const float4*>(src)[i];
    __nv_bfloat16 h0 = __float2bfloat16(v.x);
    __nv_bfloat16 h1 = __float2bfloat16(v.y);
    __nv_bfloat16 h2 = __float2bfloat16(v.z);
    __nv_bfloat16 h3 = __float2bfloat16(v.w);
    __nv_bfloat16 l0 = __float2bfloat16(v.x - __bfloat162float(h0));
    __nv_bfloat16 l1 = __float2bfloat16(v.y - __bfloat162float(h1));
    __nv_bfloat16 l2 = __float2bfloat16(v.z - __bfloat162float(h2));
    __nv_bfloat16 l3 = __float2bfloat16(v.w - __bfloat162float(h3));
    __nv_bfloat162* hp = reinterpret_cast<__nv_bfloat162*>(hi);
    __nv_bfloat162* lp = reinterpret_cast<__nv_bfloat162*>(lo);
    hp[2 * i]     = __halves2bfloat162(h0, h1);
    hp[2 * i + 1] = __halves2bfloat162(h2, h3);
    lp[2 * i]     = __halves2bfloat162(l0, l1);
    lp[2 * i + 1] = __halves2bfloat162(l2, l3);
}

// ---------------- Kernel B: split-bf16 HMMA GEMM ---------------------------
// C[M,256] = A[M,256] @ W[256,256]^T  via  Ah*Wh + Ah*Wl + Al*Wh
// CTA tile 128x128, K-chunk 32, 8 warps (warp tile 64x32), cp.async 2-stage.
//
// smem per stage (bytes): Ah 10240 | Al 10240 | Wh 10240 | Wl 10240 = 40960
// rows padded: 32 bf16 + 8 pad = 40 bf16 = 80B row stride
#define STAGE_BYTES 40960
#define ROWB 80

__global__ __launch_bounds__(256, 1)
void gemm_hmma_kernel(int M)
{
    extern __shared__ char smem[];
    const uint32_t sbase = smem_u32(smem);
    const int tid  = threadIdx.x;
    const int lane = tid & 31;
    const int wid  = tid >> 5;
    const int row0 = blockIdx.y * 128;
    const int n0c  = blockIdx.x * 128;
    const int wm   = (wid >> 2) * 64;   // warp m offset in tile
    const int wn   = (wid & 3) * 32;    // warp n offset in tile

    float acc[4][4][4];
    #pragma unroll
    for (int mt = 0; mt < 4; mt++)
        #pragma unroll
        for (int nt = 0; nt < 4; nt++)
            #pragma unroll
            for (int r = 0; r < 4; r++) acc[mt][nt][r] = 0.f;

    // ---- stage loader: 4 tiles x 512 16B-chunks = 2048 chunks / 256 thr ----
    auto load_stage = [&](int chunk, int stage) {
        #pragma unroll
        for (int j = 0; j < 8; j++) {
            int t    = tid + j * 256;
            int tile = t >> 9;        // 0:Ah 1:Al 2:Wh 3:Wl
            int c    = t & 511;
            int row  = c >> 2;
            int seg  = c & 3;
            const __nv_bfloat16* gp;
            int grow;
            if (tile < 2) {
                grow = row0 + row;
                gp = (tile == 0 ? g_A_hi : g_A_lo);
            } else {
                grow = n0c + row;
                gp = (tile == 2 ? g_W_hi : g_W_lo);
            }
            gp += (size_t)grow * IN_F + chunk * 32 + seg * 8;
            uint32_t sa = sbase + stage * STAGE_BYTES + tile * 10240
                        + row * ROWB + seg * 16;
            int ok = (tile >= 2 || grow < M) ? 16 : 0;
            CP_ASYNC16(sa, gp, ok);
        }
        asm volatile("cp.async.commit_group;");
    };

    auto compute = [&](int stage) {
        const uint32_t sb = sbase + stage * STAGE_BYTES;
        #pragma unroll
        for (int ks = 0; ks < 2; ks++) {
            const int k0 = ks * 16;
            uint32_t ah[4][4], al[4][4], bh[2][4], bl[2][4];
            // A fragments: row = wm + mt*16 + (lane&15), col8 = (lane>>4)*8
            #pragma unroll
            for (int mt = 0; mt < 4; mt++) {
                int r = wm + mt * 16 + (lane & 15);
                int c = k0 + ((lane >> 4) << 3);
                uint32_t off = sb + r * ROWB + c * 2;
                LDSM_X4(ah[mt], off);
                LDSM_X4(al[mt], off + 10240);
            }
            // B fragments: matid = lane>>3; n = p*16 + (matid>>1)*8 + (lane&7)
            //              k = k0 + (matid&1)*8
            #pragma unroll
            for (int p = 0; p < 2; p++) {
                int matid = lane >> 3;
                int nr = wn + p * 16 + ((matid >> 1) << 3) + (lane & 7);
                int kc = k0 + ((matid & 1) << 3);
                uint32_t off = sb + 20480 + nr * ROWB + kc * 2;
                LDSM_X4(bh[p], off);
                LDSM_X4(bl[p], off + 10240);
            }
            #pragma unroll
            for (int mt = 0; mt < 4; mt++) {
                #pragma unroll
                for (int nt = 0; nt < 4; nt++) {
                    uint32_t b0h = bh[nt >> 1][(nt & 1) * 2];
                    uint32_t b1h = bh[nt >> 1][(nt & 1) * 2 + 1];
                    uint32_t b0l = bl[nt >> 1][(nt & 1) * 2];
                    uint32_t b1l = bl[nt >> 1][(nt & 1) * 2 + 1];
                    MMA_BF16(acc[mt][nt], ah[mt], b0h, b1h);   // hi*hi
                    MMA_BF16(acc[mt][nt], ah[mt], b0l, b1l);   // hi*lo
                    MMA_BF16(acc[mt][nt], al[mt], b0h, b1h);   // lo*hi
                }
            }
        }
    };

    load_stage(0, 0);
    #pragma unroll 1
    for (int ch = 0; ch < 8; ch++) {
        if (ch < 7) {
            load_stage(ch + 1, (ch + 1) & 1);
            asm volatile("cp.async.wait_group 1;");
        } else {
            asm volatile("cp.async.wait_group 0;");
        }
        __syncthreads();
        compute(ch & 1);
        __syncthreads();
    }

    // ---- epilogue: fp32 stores to g_feat_src -------------------------------
    #pragma unroll
    for (int mt = 0; mt < 4; mt++) {
        int m = row0 + wm + mt * 16 + (lane >> 2);
        #pragma unroll
        for (int nt = 0; nt < 4; nt++) {
            int n = n0c + wn + nt * 8 + (lane & 3) * 2;
            if (m < M) {
                float2 v = make_float2(acc[mt][nt][0], acc[mt][nt][1]);
                *reinterpret_cast<float2*>(g_feat_src + (size_t)m * HD + n) = v;
            }
            if (m + 8 < M) {
                float2 v = make_float2(acc[mt][nt][2], acc[mt][nt][3]);
                *reinterpret_cast<float2*>(g_feat_src + (size_t)(m + 8) * HD + n) = v;
            }
        }
    }
}

// ---------------- Kernel C: el/er dot products -----------------------------
__global__ void el_er_kernel(const float* __restrict__ attn_l,
                             const float* __restrict__ attn_r, int M)
{
    int wid  = (blockIdx.x * blockDim.x + threadIdx.x) >> 5;
    int lane = threadIdx.x & 31;
    if (wid >= M * NH) return;
    int n = wid >> 2;
    int h = wid & 3;

    const float* p = g_feat_src + (size_t)n * HD + h * DH;
    float v0 = p[lane];
    float v1 = p[lane + 32];
    float al0 = attn_l[h * DH + lane],      ar0 = attn_r[h * DH + lane];
    float al1 = attn_l[h * DH + lane + 32], ar1 = attn_r[h * DH + lane + 32];
    float l = v0 * al0 + v1 * al1;
    float r = v0 * ar0 + v1 * ar1;
    #pragma unroll
    for (int o = 16; o; o >>= 1) {
        l += __shfl_xor_sync(0xffffffffu, l, o);
        r += __shfl_xor_sync(0xffffffffu, r, o);
    }
    if (lane == 0) { g_el[wid] = l; g_er[wid] = r; }
}

// ---------------- Kernel D: edge softmax + multi-head SpMM -----------------
__global__ void agg_kernel(const int* __restrict__ row_ptr,
                           const int* __restrict__ col_ind,
                           float* __restrict__ out, int M)
{
    int wid  = (blockIdx.x * blockDim.x + threadIdx.x) >> 5;
    int lane = threadIdx.x & 31;
    if (wid >= M * NH) return;
    int n = wid >> 2;
    int h = wid & 3;

    int lo  = row_ptr[n];
    int hi  = row_ptr[n + 1];
    int deg = hi - lo;

    float* op = out + (size_t)n * HD + h * DH;
    if (deg <= 0) {
        op[lane] = 0.f; op[lane + 32] = 0.f;
        return;
    }

    float eln = g_el[wid];
    float e = -INFINITY;
    int   src = 0;
    if (lane < deg) {
        src = col_ind[lo + lane];
        float x = g_er[src * NH + h] + eln;
        e = (x > 0.f) ? x : NEG_SLOPE * x;
    }
    float m = e;
    #pragma unroll
    for (int o = 16; o; o >>= 1) m = fmaxf(m, __shfl_xor_sync(0xffffffffu, m, o));
    float p = (lane < deg) ? __expf(e - m) : 0.f;
    float s = p;
    #pragma unroll
    for (int o = 16; o; o >>= 1) s += __shfl_xor_sync(0xffffffffu, s, o);
    float inv = 1.f / s;

    float acc0 = 0.f, acc1 = 0.f;
    #pragma unroll 4
    for (int j = 0; j < deg; j++) {
        float a  = __shfl_sync(0xffffffffu, p, j) * inv;
        int   sj = __shfl_sync(0xffffffffu, src, j);
        const float* q = g_feat_src + (size_t)sj * HD + h * DH;
        acc0 = fmaf(a, q[lane],      acc0);
        acc1 = fmaf(a, q[lane + 32], acc1);
    }
    op[lane]      = acc0;
    op[lane + 32] = acc1;
}

// ---------------- launch ---------------------------------------------------
extern "C" void kernel_launch(void* const* d_in, const int* in_sizes, int n_in,
                              void* d_out, int out_size)
{
    const int*   row_ptr = (const int*)  d_in[0];
    const int*   col_ind = (const int*)  d_in[1];
    const float* feat    = (const float*)d_in[2];
    const float* W       = (const float*)d_in[3];
    const float* attn_l  = (const float*)d_in[4];
    const float* attn_r  = (const float*)d_in[5];
    float* out = (float*)d_out;

    int M = in_sizes[0] - 1;   // number of nodes

    void *a_hi, *a_lo, *w_hi, *w_lo;
    cudaGetSymbolAddress(&a_hi, g_A_hi);
    cudaGetSymbolAddress(&a_lo, g_A_lo);
    cudaGetSymbolAddress(&w_hi, g_W_hi);
    cudaGetSymbolAddress(&w_lo, g_W_lo);

    // 1) bf16 hi/lo splits of feat and W
    {
        int n4 = in_sizes[2] / 4;
        convert_kernel<<<(n4 + 255) / 256, 256>>>(
            feat, (__nv_bfloat16*)a_hi, (__nv_bfloat16*)a_lo, n4);
        int w4 = in_sizes[3] / 4;
        convert_kernel<<<(w4 + 255) / 256, 256>>>(
            W, (__nv_bfloat16*)w_hi, (__nv_bfloat16*)w_lo, w4);
    }

    // 2) split-bf16 HMMA GEMM
    {
        static int smem_set = 0;
        if (!smem_set) {
            cudaFuncSetAttribute(gemm_hmma_kernel,
                                 cudaFuncAttributeMaxDynamicSharedMemorySize,
                                 2 * STAGE_BYTES);
            smem_set = 1;
        }
        dim3 grid(HD / 128, (M + 127) / 128);
        gemm_hmma_kernel<<<grid, 256, 2 * STAGE_BYTES>>>(M);
    }

    // 3) el / er
    {
        int warps = M * NH;
        int blocks = (warps * 32 + 255) / 256;
        el_er_kernel<<<blocks, 256>>>(attn_l, attn_r, M);
    }

    // 4) edge softmax + aggregate
    {
        int warps = M * NH;
        int blocks = (warps * 32 + 255) / 256;
        agg_kernel<<<blocks, 256>>>(row_ptr, col_ind, out, M);
    }
}

// round 4
// speedup vs baseline: 1.9061x; 1.3268x over previous
#include <cuda_runtime.h>
#include <cuda_bf16.h>
#include <cstdint>
#include <math.h>

// Problem constants (fixed by the dataset)
#define N_NODES 100000
#define IN_F    256
#define HD      256
#define NH      4
#define DH      64
#define NEG_SLOPE 0.2f

// ---------------- scratch (device globals; no allocation allowed) ----------
__device__ float g_feat_src[(size_t)N_NODES * HD];   // 102.4 MB
__device__ float g_el[N_NODES * NH];
__device__ float g_er[N_NODES * NH];
__device__ __nv_bfloat16 g_A_hi[(size_t)N_NODES * IN_F];
__device__ __nv_bfloat16 g_A_lo[(size_t)N_NODES * IN_F];
__device__ __nv_bfloat16 g_W_hi[HD * IN_F];
__device__ __nv_bfloat16 g_W_lo[HD * IN_F];

// ---------------- helpers ---------------------------------------------------
__device__ __forceinline__ uint32_t smem_u32(const void* p) {
    uint32_t a;
    asm("{ .reg .u64 t; cvta.to.shared.u64 t, %1; cvt.u32.u64 %0, t; }"
        : "=r"(a) : "l"(p));
    return a;
}

#define LDSM_X4(r, addr)                                                      \
    asm volatile("ldmatrix.sync.aligned.m8n8.x4.shared.b16 {%0,%1,%2,%3}, [%4];" \
        : "=r"((r)[0]), "=r"((r)[1]), "=r"((r)[2]), "=r"((r)[3]) : "r"(addr))

#define MMA_BF16(d, a, b0, b1)                                                \
    asm volatile("mma.sync.aligned.m16n8k16.row.col.f32.bf16.bf16.f32 "       \
        "{%0,%1,%2,%3}, {%4,%5,%6,%7}, {%8,%9}, {%0,%1,%2,%3};"               \
        : "+f"((d)[0]), "+f"((d)[1]), "+f"((d)[2]), "+f"((d)[3])              \
        : "r"((a)[0]), "r"((a)[1]), "r"((a)[2]), "r"((a)[3]),                 \
          "r"(b0), "r"(b1))

#define CP_ASYNC16(saddr, gptr, sz)                                           \
    asm volatile("cp.async.cg.shared.global [%0], [%1], 16, %2;"              \
        :: "r"(saddr), "l"(gptr), "r"(sz))

// ---------------- Kernel A: fp32 -> bf16 hi/lo split -----------------------
__global__ void convert_kernel(const float* __restrict__ src,
                               __nv_bfloat16* __restrict__ hi,
                               __nv_bfloat16* __restrict__ lo, int n4)
{
    int i = blockIdx.x * blockDim.x + threadIdx.x;
    if (i >= n4) return;
    float4 v = reinterpret_cast<const float4*>(src)[i];
    __nv_bfloat16 h0 = __float2bfloat16(v.x);
    __nv_bfloat16 h1 = __float2bfloat16(v.y);
    __nv_bfloat16 h2 = __float2bfloat16(v.z);
    __nv_bfloat16 h3 = __float2bfloat16(v.w);
    __nv_bfloat16 l0 = __float2bfloat16(v.x - __bfloat162float(h0));
    __nv_bfloat16 l1 = __float2bfloat16(v.y - __bfloat162float(h1));
    __nv_bfloat16 l2 = __float2bfloat16(v.z - __bfloat162float(h2));
    __nv_bfloat16 l3 = __float2bfloat16(v.w - __bfloat162float(h3));
    __nv_bfloat162* hp = reinterpret_cast<__nv_bfloat162*>(hi);
    __nv_bfloat162* lp = reinterpret_cast<__nv_bfloat162*>(lo);
    hp[2 * i]     = __halves2bfloat162(h0, h1);
    hp[2 * i + 1] = __halves2bfloat162(h2, h3);
    lp[2 * i]     = __halves2bfloat162(l0, l1);
    lp[2 * i + 1] = __halves2bfloat162(l2, l3);
}

// ---------------- Kernel B: split-bf16 HMMA GEMM + fused el/er -------------
// C[M,256] = A[M,256] @ W[256,256]^T  via  Ah*Wh + Ah*Wl + Al*Wh
// CTA tile 128x128, K-chunk 32, 8 warps (warp tile 64x32), cp.async 2-stage.
#define STAGE_BYTES 40960
#define ROWB 80

__global__ __launch_bounds__(256, 1)
void gemm_hmma_kernel(const float* __restrict__ attn_l,
                      const float* __restrict__ attn_r, int M)
{
    extern __shared__ char smem[];
    const uint32_t sbase = smem_u32(smem);
    const int tid  = threadIdx.x;
    const int lane = tid & 31;
    const int wid  = tid >> 5;
    const int row0 = blockIdx.y * 128;
    const int n0c  = blockIdx.x * 128;
    const int wm   = (wid >> 2) * 64;   // warp m offset in tile
    const int wn   = (wid & 3) * 32;    // warp n offset in tile

    float acc[4][4][4];
    #pragma unroll
    for (int mt = 0; mt < 4; mt++)
        #pragma unroll
        for (int nt = 0; nt < 4; nt++)
            #pragma unroll
            for (int r = 0; r < 4; r++) acc[mt][nt][r] = 0.f;

    auto load_stage = [&](int chunk, int stage) {
        #pragma unroll
        for (int j = 0; j < 8; j++) {
            int t    = tid + j * 256;
            int tile = t >> 9;        // 0:Ah 1:Al 2:Wh 3:Wl
            int c    = t & 511;
            int row  = c >> 2;
            int seg  = c & 3;
            const __nv_bfloat16* gp;
            int grow;
            if (tile < 2) {
                grow = row0 + row;
                gp = (tile == 0 ? g_A_hi : g_A_lo);
            } else {
                grow = n0c + row;
                gp = (tile == 2 ? g_W_hi : g_W_lo);
            }
            gp += (size_t)grow * IN_F + chunk * 32 + seg * 8;
            uint32_t sa = sbase + stage * STAGE_BYTES + tile * 10240
                        + row * ROWB + seg * 16;
            int ok = (tile >= 2 || grow < M) ? 16 : 0;
            CP_ASYNC16(sa, gp, ok);
        }
        asm volatile("cp.async.commit_group;");
    };

    auto compute = [&](int stage) {
        const uint32_t sb = sbase + stage * STAGE_BYTES;
        #pragma unroll
        for (int ks = 0; ks < 2; ks++) {
            const int k0 = ks * 16;
            uint32_t ah[4][4], al[4][4], bh[2][4], bl[2][4];
            #pragma unroll
            for (int mt = 0; mt < 4; mt++) {
                int r = wm + mt * 16 + (lane & 15);
                int c = k0 + ((lane >> 4) << 3);
                uint32_t off = sb + r * ROWB + c * 2;
                LDSM_X4(ah[mt], off);
                LDSM_X4(al[mt], off + 10240);
            }
            #pragma unroll
            for (int p = 0; p < 2; p++) {
                int matid = lane >> 3;
                int nr = wn + p * 16 + ((matid >> 1) << 3) + (lane & 7);
                int kc = k0 + ((matid & 1) << 3);
                uint32_t off = sb + 20480 + nr * ROWB + kc * 2;
                LDSM_X4(bh[p], off);
                LDSM_X4(bl[p], off + 10240);
            }
            #pragma unroll
            for (int mt = 0; mt < 4; mt++) {
                #pragma unroll
                for (int nt = 0; nt < 4; nt++) {
                    uint32_t b0h = bh[nt >> 1][(nt & 1) * 2];
                    uint32_t b1h = bh[nt >> 1][(nt & 1) * 2 + 1];
                    uint32_t b0l = bl[nt >> 1][(nt & 1) * 2];
                    uint32_t b1l = bl[nt >> 1][(nt & 1) * 2 + 1];
                    MMA_BF16(acc[mt][nt], ah[mt], b0h, b1h);   // hi*hi
                    MMA_BF16(acc[mt][nt], ah[mt], b0l, b1l);   // hi*lo
                    MMA_BF16(acc[mt][nt], al[mt], b0h, b1h);   // lo*hi
                }
            }
        }
    };

    load_stage(0, 0);
    #pragma unroll 1
    for (int ch = 0; ch < 8; ch++) {
        if (ch < 7) {
            load_stage(ch + 1, (ch + 1) & 1);
            asm volatile("cp.async.wait_group 1;");
        } else {
            asm volatile("cp.async.wait_group 0;");
        }
        __syncthreads();
        compute(ch & 1);
        __syncthreads();
    }

    // ---- epilogue 1: fp32 stores to g_feat_src -----------------------------
    #pragma unroll
    for (int mt = 0; mt < 4; mt++) {
        int m = row0 + wm + mt * 16 + (lane >> 2);
        #pragma unroll
        for (int nt = 0; nt < 4; nt++) {
            int n = n0c + wn + nt * 8 + (lane & 3) * 2;
            if (m < M) {
                float2 v = make_float2(acc[mt][nt][0], acc[mt][nt][1]);
                *reinterpret_cast<float2*>(g_feat_src + (size_t)m * HD + n) = v;
            }
            if (m + 8 < M) {
                float2 v = make_float2(acc[mt][nt][2], acc[mt][nt][3]);
                *reinterpret_cast<float2*>(g_feat_src + (size_t)(m + 8) * HD + n) = v;
            }
        }
    }

    // ---- epilogue 2: fused el/er (deterministic smem reduction) ------------
    // Warp covers cols [n0c+wn, +32) -> exactly one head; two warps (halves)
    // per (row, head) inside this CTA.
    float* s_el = reinterpret_cast<float*>(smem);           // [128][2][2]
    float* s_er = s_el + 512;                               // [128][2][2]
    const int head_local = wn >> 6;      // 0 or 1
    const int half       = (wn >> 5) & 1;

    #pragma unroll
    for (int mt = 0; mt < 4; mt++) {
        float el0 = 0.f, er0 = 0.f, el1 = 0.f, er1 = 0.f;
        #pragma unroll
        for (int nt = 0; nt < 4; nt++) {
            int c = n0c + wn + nt * 8 + (lane & 3) * 2;
            float al0 = __ldg(attn_l + c), al1 = __ldg(attn_l + c + 1);
            float ar0 = __ldg(attn_r + c), ar1 = __ldg(attn_r + c + 1);
            el0 = fmaf(acc[mt][nt][0], al0, fmaf(acc[mt][nt][1], al1, el0));
            er0 = fmaf(acc[mt][nt][0], ar0, fmaf(acc[mt][nt][1], ar1, er0));
            el1 = fmaf(acc[mt][nt][2], al0, fmaf(acc[mt][nt][3], al1, el1));
            er1 = fmaf(acc[mt][nt][2], ar0, fmaf(acc[mt][nt][3], ar1, er1));
        }
        #pragma unroll
        for (int o = 1; o < 4; o <<= 1) {
            el0 += __shfl_xor_sync(0xffffffffu, el0, o);
            er0 += __shfl_xor_sync(0xffffffffu, er0, o);
            el1 += __shfl_xor_sync(0xffffffffu, el1, o);
            er1 += __shfl_xor_sync(0xffffffffu, er1, o);
        }
        if ((lane & 3) == 0) {
            int r = wm + mt * 16 + (lane >> 2);
            s_el[(r * 2 + head_local) * 2 + half] = el0;
            s_er[(r * 2 + head_local) * 2 + half] = er0;
            s_el[((r + 8) * 2 + head_local) * 2 + half] = el1;
            s_er[((r + 8) * 2 + head_local) * 2 + half] = er1;
        }
    }
    __syncthreads();
    {
        int row = tid >> 1;          // 0..127
        int hl  = tid & 1;           // head-local
        int gr  = row0 + row;
        if (gr < M) {
            int idx = (row * 2 + hl) * 2;
            float vl = s_el[idx] + s_el[idx + 1];
            float vr = s_er[idx] + s_er[idx + 1];
            int h = (n0c >> 6) + hl;
            g_el[gr * NH + h] = vl;
            g_er[gr * NH + h] = vr;
        }
    }
}

// ---------------- Kernel C: edge softmax + SpMM (warp per node) ------------
__global__ __launch_bounds__(256)
void agg_kernel(const int* __restrict__ row_ptr,
                const int* __restrict__ col_ind,
                float* __restrict__ out, int M)
{
    __shared__ float s_a[8][32][4];
    const int w    = threadIdx.x >> 5;
    const int lane = threadIdx.x & 31;
    const int n    = blockIdx.x * 8 + w;
    if (n >= M) return;

    const int lo  = row_ptr[n];
    const int deg = row_ptr[n + 1] - lo;
    float* op = out + (size_t)n * HD + lane * 8;

    if (deg <= 0) {
        float4 z = make_float4(0.f, 0.f, 0.f, 0.f);
        *reinterpret_cast<float4*>(op)     = z;
        *reinterpret_cast<float4*>(op + 4) = z;
        return;
    }

    // e[h] per edge (lane = edge index)
    int src = 0;
    float4 e4 = make_float4(-INFINITY, -INFINITY, -INFINITY, -INFINITY);
    float4 el4 = *reinterpret_cast<const float4*>(g_el + n * NH);
    if (lane < deg) {
        src = col_ind[lo + lane];
        float4 er4 = *reinterpret_cast<const float4*>(g_er + src * NH);
        float x;
        x = er4.x + el4.x; e4.x = (x > 0.f) ? x : NEG_SLOPE * x;
        x = er4.y + el4.y; e4.y = (x > 0.f) ? x : NEG_SLOPE * x;
        x = er4.z + el4.z; e4.z = (x > 0.f) ? x : NEG_SLOPE * x;
        x = er4.w + el4.w; e4.w = (x > 0.f) ? x : NEG_SLOPE * x;
    }
    // per-head max over edges
    float4 mx = e4;
    #pragma unroll
    for (int o = 16; o; o >>= 1) {
        mx.x = fmaxf(mx.x, __shfl_xor_sync(0xffffffffu, mx.x, o));
        mx.y = fmaxf(mx.y, __shfl_xor_sync(0xffffffffu, mx.y, o));
        mx.z = fmaxf(mx.z, __shfl_xor_sync(0xffffffffu, mx.z, o));
        mx.w = fmaxf(mx.w, __shfl_xor_sync(0xffffffffu, mx.w, o));
    }
    float4 p = make_float4(0.f, 0.f, 0.f, 0.f);
    if (lane < deg) {
        p.x = __expf(e4.x - mx.x);
        p.y = __expf(e4.y - mx.y);
        p.z = __expf(e4.z - mx.z);
        p.w = __expf(e4.w - mx.w);
    }
    float4 s = p;
    #pragma unroll
    for (int o = 16; o; o >>= 1) {
        s.x += __shfl_xor_sync(0xffffffffu, s.x, o);
        s.y += __shfl_xor_sync(0xffffffffu, s.y, o);
        s.z += __shfl_xor_sync(0xffffffffu, s.z, o);
        s.w += __shfl_xor_sync(0xffffffffu, s.w, o);
    }
    p.x /= s.x; p.y /= s.y; p.z /= s.z; p.w /= s.w;
    *reinterpret_cast<float4*>(&s_a[w][lane][0]) = p;
    __syncwarp();

    // SpMM: lane covers cols [lane*8, lane*8+8), all within head (lane>>3)
    const int hsel = lane >> 3;
    float acc[8];
    #pragma unroll
    for (int i = 0; i < 8; i++) acc[i] = 0.f;

    #pragma unroll 4
    for (int j = 0; j < deg; j++) {
        int   sj = __shfl_sync(0xffffffffu, src, j);
        float a  = s_a[w][j][hsel];
        const float4* q = reinterpret_cast<const float4*>(
            g_feat_src + (size_t)sj * HD + lane * 8);
        float4 q0 = q[0];
        float4 q1 = q[1];
        acc[0] = fmaf(a, q0.x, acc[0]);
        acc[1] = fmaf(a, q0.y, acc[1]);
        acc[2] = fmaf(a, q0.z, acc[2]);
        acc[3] = fmaf(a, q0.w, acc[3]);
        acc[4] = fmaf(a, q1.x, acc[4]);
        acc[5] = fmaf(a, q1.y, acc[5]);
        acc[6] = fmaf(a, q1.z, acc[6]);
        acc[7] = fmaf(a, q1.w, acc[7]);
    }
    *reinterpret_cast<float4*>(op)     = make_float4(acc[0], acc[1], acc[2], acc[3]);
    *reinterpret_cast<float4*>(op + 4) = make_float4(acc[4], acc[5], acc[6], acc[7]);
}

// ---------------- launch ---------------------------------------------------
extern "C" void kernel_launch(void* const* d_in, const int* in_sizes, int n_in,
                              void* d_out, int out_size)
{
    const int*   row_ptr = (const int*)  d_in[0];
    const int*   col_ind = (const int*)  d_in[1];
    const float* feat    = (const float*)d_in[2];
    const float* W       = (const float*)d_in[3];
    const float* attn_l  = (const float*)d_in[4];
    const float* attn_r  = (const float*)d_in[5];
    float* out = (float*)d_out;

    int M = in_sizes[0] - 1;   // number of nodes

    void *a_hi, *a_lo, *w_hi, *w_lo;
    cudaGetSymbolAddress(&a_hi, g_A_hi);
    cudaGetSymbolAddress(&a_lo, g_A_lo);
    cudaGetSymbolAddress(&w_hi, g_W_hi);
    cudaGetSymbolAddress(&w_lo, g_W_lo);

    // 1) bf16 hi/lo splits of feat and W
    {
        int n4 = in_sizes[2] / 4;
        convert_kernel<<<(n4 + 255) / 256, 256>>>(
            feat, (__nv_bfloat16*)a_hi, (__nv_bfloat16*)a_lo, n4);
        int w4 = in_sizes[3] / 4;
        convert_kernel<<<(w4 + 255) / 256, 256>>>(
            W, (__nv_bfloat16*)w_hi, (__nv_bfloat16*)w_lo, w4);
    }

    // 2) split-bf16 HMMA GEMM with fused el/er epilogue
    {
        static int smem_set = 0;
        if (!smem_set) {
            cudaFuncSetAttribute(gemm_hmma_kernel,
                                 cudaFuncAttributeMaxDynamicSharedMemorySize,
                                 2 * STAGE_BYTES);
            smem_set = 1;
        }
        dim3 grid(HD / 128, (M + 127) / 128);
        gemm_hmma_kernel<<<grid, 256, 2 * STAGE_BYTES>>>(attn_l, attn_r, M);
    }

    // 3) edge softmax + aggregate (warp per node)
    {
        int blocks = (M + 7) / 8;
        agg_kernel<<<blocks, 256>>>(row_ptr, col_ind, out, M);
    }
}

// round 6
// speedup vs baseline: 2.1125x; 1.1082x over previous
#include <cuda_runtime.h>
#include <cuda_bf16.h>
#include <cstdint>
#include <math.h>

// Problem constants (fixed by the dataset)
#define N_NODES 100000
#define IN_F    256
#define HD      256
#define NH      4
#define DH      64
#define NEG_SLOPE 0.2f

// ---------------- scratch (device globals; no allocation allowed) ----------
__device__ float g_feat_src[(size_t)N_NODES * HD];   // 102.4 MB
__device__ float g_el[N_NODES * NH];
__device__ float g_er[N_NODES * NH];
__device__ __nv_bfloat16 g_A_hi[(size_t)N_NODES * IN_F];
__device__ __nv_bfloat16 g_A_lo[(size_t)N_NODES * IN_F];
__device__ __nv_bfloat16 g_W_hi[HD * IN_F];
__device__ __nv_bfloat16 g_W_lo[HD * IN_F];

// ---------------- helpers ---------------------------------------------------
__device__ __forceinline__ uint32_t smem_u32(const void* p) {
    uint32_t a;
    asm("{ .reg .u64 t; cvta.to.shared.u64 t, %1; cvt.u32.u64 %0, t; }"
        : "=r"(a) : "l"(p));
    return a;
}

#define LDSM_X4(r, addr)                                                      \
    asm volatile("ldmatrix.sync.aligned.m8n8.x4.shared.b16 {%0,%1,%2,%3}, [%4];" \
        : "=r"((r)[0]), "=r"((r)[1]), "=r"((r)[2]), "=r"((r)[3]) : "r"(addr))

#define MMA_BF16(d, a, b0, b1)                                                \
    asm volatile("mma.sync.aligned.m16n8k16.row.col.f32.bf16.bf16.f32 "       \
        "{%0,%1,%2,%3}, {%4,%5,%6,%7}, {%8,%9}, {%0,%1,%2,%3};"               \
        : "+f"((d)[0]), "+f"((d)[1]), "+f"((d)[2]), "+f"((d)[3])              \
        : "r"((a)[0]), "r"((a)[1]), "r"((a)[2]), "r"((a)[3]),                 \
          "r"(b0), "r"(b1))

#define CP_ASYNC16(saddr, gptr, sz)                                           \
    asm volatile("cp.async.cg.shared.global [%0], [%1], 16, %2;"              \
        :: "r"(saddr), "l"(gptr), "r"(sz))

// 256-bit gather load pinning lines in L2 (only legal evict_last ld width)
__device__ __forceinline__ void ldg256_evict_last(const float* p, uint32_t* v) {
    asm volatile(
        "ld.global.nc.L2::evict_last.v8.b32 {%0,%1,%2,%3,%4,%5,%6,%7}, [%8];"
        : "=r"(v[0]), "=r"(v[1]), "=r"(v[2]), "=r"(v[3]),
          "=r"(v[4]), "=r"(v[5]), "=r"(v[6]), "=r"(v[7])
        : "l"(p));
}

// ---------------- Kernel A: fp32 -> bf16 hi/lo split -----------------------
__global__ void convert_kernel(const float* __restrict__ src,
                               __nv_bfloat16* __restrict__ hi,
                               __nv_bfloat16* __restrict__ lo, int n4)
{
    int i = blockIdx.x * blockDim.x + threadIdx.x;
    if (i >= n4) return;
    float4 v = reinterpret_cast<const float4*>(src)[i];
    __nv_bfloat16 h0 = __float2bfloat16(v.x);
    __nv_bfloat16 h1 = __float2bfloat16(v.y);
    __nv_bfloat16 h2 = __float2bfloat16(v.z);
    __nv_bfloat16 h3 = __float2bfloat16(v.w);
    __nv_bfloat16 l0 = __float2bfloat16(v.x - __bfloat162float(h0));
    __nv_bfloat16 l1 = __float2bfloat16(v.y - __bfloat162float(h1));
    __nv_bfloat16 l2 = __float2bfloat16(v.z - __bfloat162float(h2));
    __nv_bfloat16 l3 = __float2bfloat16(v.w - __bfloat162float(h3));
    __nv_bfloat162* hp = reinterpret_cast<__nv_bfloat162*>(hi);
    __nv_bfloat162* lp = reinterpret_cast<__nv_bfloat162*>(lo);
    hp[2 * i]     = __halves2bfloat162(h0, h1);
    hp[2 * i + 1] = __halves2bfloat162(h2, h3);
    lp[2 * i]     = __halves2bfloat162(l0, l1);
    lp[2 * i + 1] = __halves2bfloat162(l2, l3);
}

// ---------------- Kernel B: split-bf16 HMMA GEMM + fused el/er -------------
#define STAGE_BYTES 40960
#define ROWB 80

__global__ __launch_bounds__(256, 2)
void gemm_hmma_kernel(const float* __restrict__ attn_l,
                      const float* __restrict__ attn_r, int M)
{
    extern __shared__ char smem[];
    const uint32_t sbase = smem_u32(smem);
    const int tid  = threadIdx.x;
    const int lane = tid & 31;
    const int wid  = tid >> 5;
    const int row0 = blockIdx.y * 128;
    const int n0c  = blockIdx.x * 128;
    const int wm   = (wid >> 2) * 64;
    const int wn   = (wid & 3) * 32;

    float acc[4][4][4];
    #pragma unroll
    for (int mt = 0; mt < 4; mt++)
        #pragma unroll
        for (int nt = 0; nt < 4; nt++)
            #pragma unroll
            for (int r = 0; r < 4; r++) acc[mt][nt][r] = 0.f;

    auto load_stage = [&](int chunk, int stage) {
        #pragma unroll
        for (int j = 0; j < 8; j++) {
            int t    = tid + j * 256;
            int tile = t >> 9;        // 0:Ah 1:Al 2:Wh 3:Wl
            int c    = t & 511;
            int row  = c >> 2;
            int seg  = c & 3;
            const __nv_bfloat16* gp;
            int grow;
            if (tile < 2) {
                grow = row0 + row;
                gp = (tile == 0 ? g_A_hi : g_A_lo);
            } else {
                grow = n0c + row;
                gp = (tile == 2 ? g_W_hi : g_W_lo);
            }
            gp += (size_t)grow * IN_F + chunk * 32 + seg * 8;
            uint32_t sa = sbase + stage * STAGE_BYTES + tile * 10240
                        + row * ROWB + seg * 16;
            int ok = (tile >= 2 || grow < M) ? 16 : 0;
            CP_ASYNC16(sa, gp, ok);
        }
        asm volatile("cp.async.commit_group;");
    };

    auto compute = [&](int stage) {
        const uint32_t sb = sbase + stage * STAGE_BYTES;
        #pragma unroll
        for (int ks = 0; ks < 2; ks++) {
            const int k0 = ks * 16;
            uint32_t ah[4][4], al[4][4], bh[2][4], bl[2][4];
            #pragma unroll
            for (int mt = 0; mt < 4; mt++) {
                int r = wm + mt * 16 + (lane & 15);
                int c = k0 + ((lane >> 4) << 3);
                uint32_t off = sb + r * ROWB + c * 2;
                LDSM_X4(ah[mt], off);
                LDSM_X4(al[mt], off + 10240);
            }
            #pragma unroll
            for (int p = 0; p < 2; p++) {
                int matid = lane >> 3;
                int nr = wn + p * 16 + ((matid >> 1) << 3) + (lane & 7);
                int kc = k0 + ((matid & 1) << 3);
                uint32_t off = sb + 20480 + nr * ROWB + kc * 2;
                LDSM_X4(bh[p], off);
                LDSM_X4(bl[p], off + 10240);
            }
            #pragma unroll
            for (int mt = 0; mt < 4; mt++) {
                #pragma unroll
                for (int nt = 0; nt < 4; nt++) {
                    uint32_t b0h = bh[nt >> 1][(nt & 1) * 2];
                    uint32_t b1h = bh[nt >> 1][(nt & 1) * 2 + 1];
                    uint32_t b0l = bl[nt >> 1][(nt & 1) * 2];
                    uint32_t b1l = bl[nt >> 1][(nt & 1) * 2 + 1];
                    MMA_BF16(acc[mt][nt], ah[mt], b0h, b1h);   // hi*hi
                    MMA_BF16(acc[mt][nt], ah[mt], b0l, b1l);   // hi*lo
                    MMA_BF16(acc[mt][nt], al[mt], b0h, b1h);   // lo*hi
                }
            }
        }
    };

    load_stage(0, 0);
    #pragma unroll 1
    for (int ch = 0; ch < 8; ch++) {
        if (ch < 7) {
            load_stage(ch + 1, (ch + 1) & 1);
            asm volatile("cp.async.wait_group 1;");
        } else {
            asm volatile("cp.async.wait_group 0;");
        }
        __syncthreads();
        compute(ch & 1);
        __syncthreads();
    }

    // ---- epilogue 1: fp32 stores to g_feat_src -----------------------------
    #pragma unroll
    for (int mt = 0; mt < 4; mt++) {
        int m = row0 + wm + mt * 16 + (lane >> 2);
        #pragma unroll
        for (int nt = 0; nt < 4; nt++) {
            int n = n0c + wn + nt * 8 + (lane & 3) * 2;
            if (m < M) {
                float2 v = make_float2(acc[mt][nt][0], acc[mt][nt][1]);
                *reinterpret_cast<float2*>(g_feat_src + (size_t)m * HD + n) = v;
            }
            if (m + 8 < M) {
                float2 v = make_float2(acc[mt][nt][2], acc[mt][nt][3]);
                *reinterpret_cast<float2*>(g_feat_src + (size_t)(m + 8) * HD + n) = v;
            }
        }
    }

    // ---- epilogue 2: fused el/er (deterministic smem reduction) ------------
    float* s_el = reinterpret_cast<float*>(smem);           // [128][2][2]
    float* s_er = s_el + 512;                               // [128][2][2]
    const int head_local = wn >> 6;
    const int half       = (wn >> 5) & 1;

    #pragma unroll
    for (int mt = 0; mt < 4; mt++) {
        float el0 = 0.f, er0 = 0.f, el1 = 0.f, er1 = 0.f;
        #pragma unroll
        for (int nt = 0; nt < 4; nt++) {
            int c = n0c + wn + nt * 8 + (lane & 3) * 2;
            float al0 = __ldg(attn_l + c), al1 = __ldg(attn_l + c + 1);
            float ar0 = __ldg(attn_r + c), ar1 = __ldg(attn_r + c + 1);
            el0 = fmaf(acc[mt][nt][0], al0, fmaf(acc[mt][nt][1], al1, el0));
            er0 = fmaf(acc[mt][nt][0], ar0, fmaf(acc[mt][nt][1], ar1, er0));
            el1 = fmaf(acc[mt][nt][2], al0, fmaf(acc[mt][nt][3], al1, el1));
            er1 = fmaf(acc[mt][nt][2], ar0, fmaf(acc[mt][nt][3], ar1, er1));
        }
        #pragma unroll
        for (int o = 1; o < 4; o <<= 1) {
            el0 += __shfl_xor_sync(0xffffffffu, el0, o);
            er0 += __shfl_xor_sync(0xffffffffu, er0, o);
            el1 += __shfl_xor_sync(0xffffffffu, el1, o);
            er1 += __shfl_xor_sync(0xffffffffu, er1, o);
        }
        if ((lane & 3) == 0) {
            int r = wm + mt * 16 + (lane >> 2);
            s_el[(r * 2 + head_local) * 2 + half] = el0;
            s_er[(r * 2 + head_local) * 2 + half] = er0;
            s_el[((r + 8) * 2 + head_local) * 2 + half] = el1;
            s_er[((r + 8) * 2 + head_local) * 2 + half] = er1;
        }
    }
    __syncthreads();
    {
        int row = tid >> 1;
        int hl  = tid & 1;
        int gr  = row0 + row;
        if (gr < M) {
            int idx = (row * 2 + hl) * 2;
            float vl = s_el[idx] + s_el[idx + 1];
            float vr = s_er[idx] + s_er[idx + 1];
            int h = (n0c >> 6) + hl;
            g_el[gr * NH + h] = vl;
            g_er[gr * NH + h] = vr;
        }
    }
}

// ---------------- Kernel C: edge softmax + SpMM (warp per node) ------------
// Lane owns 8 contiguous cols (32 lanes x 32B = full 1KB row); 256-bit
// evict_last gathers keep feat_src resident in L2.
__global__ __launch_bounds__(256)
void agg_kernel(const int* __restrict__ row_ptr,
                const int* __restrict__ col_ind,
                float* __restrict__ out, int M)
{
    __shared__ float s_a[8][32][4];
    __shared__ int   s_src[8][32];
    const int w    = threadIdx.x >> 5;
    const int lane = threadIdx.x & 31;
    const int n    = blockIdx.x * 8 + w;
    if (n >= M) return;

    const int lo  = row_ptr[n];
    const int deg = row_ptr[n + 1] - lo;
    float* op = out + (size_t)n * HD + lane * 8;

    if (deg <= 0) {
        float4 z = make_float4(0.f, 0.f, 0.f, 0.f);
        *reinterpret_cast<float4*>(op)     = z;
        *reinterpret_cast<float4*>(op + 4) = z;
        return;
    }

    // ---- edge softmax (lane = edge index) ----------------------------------
    int src = 0;
    float4 e4 = make_float4(-INFINITY, -INFINITY, -INFINITY, -INFINITY);
    float4 el4 = *reinterpret_cast<const float4*>(g_el + n * NH);
    if (lane < deg) {
        src = col_ind[lo + lane];
        float4 er4 = *reinterpret_cast<const float4*>(g_er + src * NH);
        float x;
        x = er4.x + el4.x; e4.x = (x > 0.f) ? x : NEG_SLOPE * x;
        x = er4.y + el4.y; e4.y = (x > 0.f) ? x : NEG_SLOPE * x;
        x = er4.z + el4.z; e4.z = (x > 0.f) ? x : NEG_SLOPE * x;
        x = er4.w + el4.w; e4.w = (x > 0.f) ? x : NEG_SLOPE * x;
    }
    float4 mx = e4;
    #pragma unroll
    for (int o = 16; o; o >>= 1) {
        mx.x = fmaxf(mx.x, __shfl_xor_sync(0xffffffffu, mx.x, o));
        mx.y = fmaxf(mx.y, __shfl_xor_sync(0xffffffffu, mx.y, o));
        mx.z = fmaxf(mx.z, __shfl_xor_sync(0xffffffffu, mx.z, o));
        mx.w = fmaxf(mx.w, __shfl_xor_sync(0xffffffffu, mx.w, o));
    }
    float4 p = make_float4(0.f, 0.f, 0.f, 0.f);
    if (lane < deg) {
        p.x = __expf(e4.x - mx.x);
        p.y = __expf(e4.y - mx.y);
        p.z = __expf(e4.z - mx.z);
        p.w = __expf(e4.w - mx.w);
    }
    float4 s = p;
    #pragma unroll
    for (int o = 16; o; o >>= 1) {
        s.x += __shfl_xor_sync(0xffffffffu, s.x, o);
        s.y += __shfl_xor_sync(0xffffffffu, s.y, o);
        s.z += __shfl_xor_sync(0xffffffffu, s.z, o);
        s.w += __shfl_xor_sync(0xffffffffu, s.w, o);
    }
    p.x /= s.x; p.y /= s.y; p.z /= s.z; p.w /= s.w;
    if (lane < deg) {
        *reinterpret_cast<float4*>(&s_a[w][lane][0]) = p;
        s_src[w][lane] = src;
    }
    __syncwarp();

    // ---- SpMM: lane covers cols [lane*8, +8); head = lane>>3 ---------------
    const int hsel = lane >> 3;
    const float* base = g_feat_src + lane * 8;
    float acc[8];
    #pragma unroll
    for (int i = 0; i < 8; i++) acc[i] = 0.f;

    if (deg == 16) {
        #pragma unroll
        for (int j = 0; j < 16; j++) {
            int   sj = s_src[w][j];
            float a  = s_a[w][j][hsel];
            uint32_t q[8];
            ldg256_evict_last(base + (size_t)sj * HD, q);
            #pragma unroll
            for (int i = 0; i < 8; i++)
                acc[i] = fmaf(a, __uint_as_float(q[i]), acc[i]);
        }
    } else {
        #pragma unroll 4
        for (int j = 0; j < deg; j++) {
            int   sj = s_src[w][j];
            float a  = s_a[w][j][hsel];
            uint32_t q[8];
            ldg256_evict_last(base + (size_t)sj * HD, q);
            #pragma unroll
            for (int i = 0; i < 8; i++)
                acc[i] = fmaf(a, __uint_as_float(q[i]), acc[i]);
        }
    }
    *reinterpret_cast<float4*>(op)     = make_float4(acc[0], acc[1], acc[2], acc[3]);
    *reinterpret_cast<float4*>(op + 4) = make_float4(acc[4], acc[5], acc[6], acc[7]);
}

// ---------------- launch ---------------------------------------------------
extern "C" void kernel_launch(void* const* d_in, const int* in_sizes, int n_in,
                              void* d_out, int out_size)
{
    const int*   row_ptr = (const int*)  d_in[0];
    const int*   col_ind = (const int*)  d_in[1];
    const float* feat    = (const float*)d_in[2];
    const float* W       = (const float*)d_in[3];
    const float* attn_l  = (const float*)d_in[4];
    const float* attn_r  = (const float*)d_in[5];
    float* out = (float*)d_out;

    int M = in_sizes[0] - 1;   // number of nodes

    void *a_hi, *a_lo, *w_hi, *w_lo;
    cudaGetSymbolAddress(&a_hi, g_A_hi);
    cudaGetSymbolAddress(&a_lo, g_A_lo);
    cudaGetSymbolAddress(&w_hi, g_W_hi);
    cudaGetSymbolAddress(&w_lo, g_W_lo);

    // 1) bf16 hi/lo splits of feat and W
    {
        int n4 = in_sizes[2] / 4;
        convert_kernel<<<(n4 + 255) / 256, 256>>>(
            feat, (__nv_bfloat16*)a_hi, (__nv_bfloat16*)a_lo, n4);
        int w4 = in_sizes[3] / 4;
        convert_kernel<<<(w4 + 255) / 256, 256>>>(
            W, (__nv_bfloat16*)w_hi, (__nv_bfloat16*)w_lo, w4);
    }

    // 2) split-bf16 HMMA GEMM with fused el/er epilogue
    {
        static int smem_set = 0;
        if (!smem_set) {
            cudaFuncSetAttribute(gemm_hmma_kernel,
                                 cudaFuncAttributeMaxDynamicSharedMemorySize,
                                 2 * STAGE_BYTES);
            smem_set = 1;
        }
        dim3 grid(HD / 128, (M + 127) / 128);
        gemm_hmma_kernel<<<grid, 256, 2 * STAGE_BYTES>>>(attn_l, attn_r, M);
    }

    // 3) edge softmax + aggregate (warp per node)
    {
        int blocks = (M + 7) / 8;
        agg_kernel<<<blocks, 256>>>(row_ptr, col_ind, out, M);
    }
}

// round 7
// speedup vs baseline: 2.3105x; 1.0937x over previous
#include <cuda_runtime.h>
#include <cuda_bf16.h>
#include <cstdint>
#include <math.h>

// Problem constants (fixed by the dataset)
#define N_NODES 100000
#define IN_F    256
#define HD      256
#define NH      4
#define DH      64
#define NEG_SLOPE 0.2f

// ---------------- scratch (device globals; no allocation allowed) ----------
__device__ float g_feat_src[(size_t)N_NODES * HD];   // 102.4 MB
__device__ float g_el[N_NODES * NH];
__device__ float g_er[N_NODES * NH];
__device__ __nv_bfloat16 g_W_hi[HD * IN_F];
__device__ __nv_bfloat16 g_W_lo[HD * IN_F];

// ---------------- helpers ---------------------------------------------------
__device__ __forceinline__ uint32_t smem_u32(const void* p) {
    uint32_t a;
    asm("{ .reg .u64 t; cvta.to.shared.u64 t, %1; cvt.u32.u64 %0, t; }"
        : "=r"(a) : "l"(p));
    return a;
}

#define LDSM_X4(r, addr)                                                      \
    asm volatile("ldmatrix.sync.aligned.m8n8.x4.shared.b16 {%0,%1,%2,%3}, [%4];" \
        : "=r"((r)[0]), "=r"((r)[1]), "=r"((r)[2]), "=r"((r)[3]) : "r"(addr))

#define MMA_BF16(d, a, b0, b1)                                                \
    asm volatile("mma.sync.aligned.m16n8k16.row.col.f32.bf16.bf16.f32 "       \
        "{%0,%1,%2,%3}, {%4,%5,%6,%7}, {%8,%9}, {%0,%1,%2,%3};"               \
        : "+f"((d)[0]), "+f"((d)[1]), "+f"((d)[2]), "+f"((d)[3])              \
        : "r"((a)[0]), "r"((a)[1]), "r"((a)[2]), "r"((a)[3]),                 \
          "r"(b0), "r"(b1))

#define CP_ASYNC16(saddr, gptr, sz)                                           \
    asm volatile("cp.async.cg.shared.global [%0], [%1], 16, %2;"              \
        :: "r"(saddr), "l"(gptr), "r"(sz))

// 256-bit gather load pinning lines in L2 (only legal evict_last ld width)
__device__ __forceinline__ void ldg256_evict_last(const float* p, uint32_t* v) {
    asm volatile(
        "ld.global.nc.L2::evict_last.v8.b32 {%0,%1,%2,%3,%4,%5,%6,%7}, [%8];"
        : "=r"(v[0]), "=r"(v[1]), "=r"(v[2]), "=r"(v[3]),
          "=r"(v[4]), "=r"(v[5]), "=r"(v[6]), "=r"(v[7])
        : "l"(p));
}
// Streaming store (evict-first) so `out` does not evict feat_src from L2
__device__ __forceinline__ void stg_cs4(float* p, float a, float b, float c, float d) {
    asm volatile("st.global.cs.v4.f32 [%0], {%1,%2,%3,%4};"
                 :: "l"(p), "f"(a), "f"(b), "f"(c), "f"(d));
}

// ---------------- Kernel A: fp32 -> bf16 hi/lo split (W only, tiny) --------
__global__ void convert_kernel(const float* __restrict__ src,
                               __nv_bfloat16* __restrict__ hi,
                               __nv_bfloat16* __restrict__ lo, int n4)
{
    int i = blockIdx.x * blockDim.x + threadIdx.x;
    if (i >= n4) return;
    float4 v = reinterpret_cast<const float4*>(src)[i];
    __nv_bfloat16 h0 = __float2bfloat16(v.x);
    __nv_bfloat16 h1 = __float2bfloat16(v.y);
    __nv_bfloat16 h2 = __float2bfloat16(v.z);
    __nv_bfloat16 h3 = __float2bfloat16(v.w);
    __nv_bfloat16 l0 = __float2bfloat16(v.x - __bfloat162float(h0));
    __nv_bfloat16 l1 = __float2bfloat16(v.y - __bfloat162float(h1));
    __nv_bfloat16 l2 = __float2bfloat16(v.z - __bfloat162float(h2));
    __nv_bfloat16 l3 = __float2bfloat16(v.w - __bfloat162float(h3));
    __nv_bfloat162* hp = reinterpret_cast<__nv_bfloat162*>(hi);
    __nv_bfloat162* lp = reinterpret_cast<__nv_bfloat162*>(lo);
    hp[2 * i]     = __halves2bfloat162(h0, h1);
    hp[2 * i + 1] = __halves2bfloat162(h2, h3);
    lp[2 * i]     = __halves2bfloat162(l0, l1);
    lp[2 * i + 1] = __halves2bfloat162(l2, l3);
}

// ---------------- Kernel B: split-bf16 HMMA GEMM + fused el/er -------------
// A loaded as fp32 from the input tensor, converted to hi/lo bf16 in regs.
#define STAGE_BYTES 40960
#define ROWB 80

__global__ __launch_bounds__(256, 2)
void gemm_hmma_kernel(const float* __restrict__ A,
                      const float* __restrict__ attn_l,
                      const float* __restrict__ attn_r, int M)
{
    extern __shared__ char smem[];
    const uint32_t sbase = smem_u32(smem);
    const int tid  = threadIdx.x;
    const int lane = tid & 31;
    const int wid  = tid >> 5;
    const int row0 = blockIdx.y * 128;
    const int n0c  = blockIdx.x * 128;
    const int wm   = (wid >> 2) * 64;
    const int wn   = (wid & 3) * 32;

    float acc[4][4][4];
    #pragma unroll
    for (int mt = 0; mt < 4; mt++)
        #pragma unroll
        for (int nt = 0; nt < 4; nt++)
            #pragma unroll
            for (int r = 0; r < 4; r++) acc[mt][nt][r] = 0.f;

    // W stage loader: Wh + Wl tiles via cp.async
    auto load_W = [&](int chunk, int stage) {
        #pragma unroll
        for (int j = 0; j < 4; j++) {
            int t    = tid + j * 256;
            int tile = t >> 9;        // 0:Wh 1:Wl
            int c    = t & 511;
            int row  = c >> 2;
            int seg  = c & 3;
            const __nv_bfloat16* gp = (tile == 0 ? g_W_hi : g_W_lo)
                + (size_t)(n0c + row) * IN_F + chunk * 32 + seg * 8;
            uint32_t sa = sbase + stage * STAGE_BYTES + 20480 + tile * 10240
                        + row * ROWB + seg * 16;
            CP_ASYNC16(sa, gp, 16);
        }
        asm volatile("cp.async.commit_group;");
    };

    // A chunk: 128 rows x 32 fp32 cols = 1024 float4 / 256 thr = 4 each
    float4 areg[4];
    auto ldg_A = [&](int chunk) {
        #pragma unroll
        for (int j = 0; j < 4; j++) {
            int idx = tid + j * 256;
            int row = idx >> 3;
            int seg = idx & 7;
            int gr  = row0 + row;
            areg[j] = (gr < M)
                ? *reinterpret_cast<const float4*>(
                      A + (size_t)gr * IN_F + chunk * 32 + seg * 4)
                : make_float4(0.f, 0.f, 0.f, 0.f);
        }
    };
    auto sts_A = [&](int stage) {
        #pragma unroll
        for (int j = 0; j < 4; j++) {
            int idx = tid + j * 256;
            int row = idx >> 3;
            int seg = idx & 7;
            float4 v = areg[j];
            __nv_bfloat16 h0 = __float2bfloat16(v.x);
            __nv_bfloat16 h1 = __float2bfloat16(v.y);
            __nv_bfloat16 h2 = __float2bfloat16(v.z);
            __nv_bfloat16 h3 = __float2bfloat16(v.w);
            __nv_bfloat162 hlo = __halves2bfloat162(h0, h1);
            __nv_bfloat162 hhi = __halves2bfloat162(h2, h3);
            __nv_bfloat162 llo = __halves2bfloat162(
                __float2bfloat16(v.x - __bfloat162float(h0)),
                __float2bfloat16(v.y - __bfloat162float(h1)));
            __nv_bfloat162 lhi = __halves2bfloat162(
                __float2bfloat16(v.z - __bfloat162float(h2)),
                __float2bfloat16(v.w - __bfloat162float(h3)));
            uint32_t off = stage * STAGE_BYTES + row * ROWB + seg * 8;
            char* base = smem + off;
            *reinterpret_cast<__nv_bfloat162*>(base)             = hlo;
            *reinterpret_cast<__nv_bfloat162*>(base + 4)         = hhi;
            *reinterpret_cast<__nv_bfloat162*>(base + 10240)     = llo;
            *reinterpret_cast<__nv_bfloat162*>(base + 10240 + 4) = lhi;
        }
    };

    auto compute = [&](int stage) {
        const uint32_t sb = sbase + stage * STAGE_BYTES;
        #pragma unroll
        for (int ks = 0; ks < 2; ks++) {
            const int k0 = ks * 16;
            uint32_t ah[4][4], al[4][4], bh[2][4], bl[2][4];
            #pragma unroll
            for (int mt = 0; mt < 4; mt++) {
                int r = wm + mt * 16 + (lane & 15);
                int c = k0 + ((lane >> 4) << 3);
                uint32_t off = sb + r * ROWB + c * 2;
                LDSM_X4(ah[mt], off);
                LDSM_X4(al[mt], off + 10240);
            }
            #pragma unroll
            for (int p = 0; p < 2; p++) {
                int matid = lane >> 3;
                int nr = wn + p * 16 + ((matid >> 1) << 3) + (lane & 7);
                int kc = k0 + ((matid & 1) << 3);
                uint32_t off = sb + 20480 + nr * ROWB + kc * 2;
                LDSM_X4(bh[p], off);
                LDSM_X4(bl[p], off + 10240);
            }
            #pragma unroll
            for (int mt = 0; mt < 4; mt++) {
                #pragma unroll
                for (int nt = 0; nt < 4; nt++) {
                    uint32_t b0h = bh[nt >> 1][(nt & 1) * 2];
                    uint32_t b1h = bh[nt >> 1][(nt & 1) * 2 + 1];
                    uint32_t b0l = bl[nt >> 1][(nt & 1) * 2];
                    uint32_t b1l = bl[nt >> 1][(nt & 1) * 2 + 1];
                    MMA_BF16(acc[mt][nt], ah[mt], b0h, b1h);   // hi*hi
                    MMA_BF16(acc[mt][nt], ah[mt], b0l, b1l);   // hi*lo
                    MMA_BF16(acc[mt][nt], al[mt], b0h, b1h);   // lo*hi
                }
            }
        }
    };

    ldg_A(0);
    load_W(0, 0);
    #pragma unroll 1
    for (int ch = 0; ch < 8; ch++) {
        const int s = ch & 1;
        if (ch < 7) {
            load_W(ch + 1, s ^ 1);
            asm volatile("cp.async.wait_group 1;");
        } else {
            asm volatile("cp.async.wait_group 0;");
        }
        sts_A(s);
        __syncthreads();
        if (ch < 7) ldg_A(ch + 1);   // overlap LDG with compute
        compute(s);
        __syncthreads();
    }

    // ---- epilogue 1: fp32 stores to g_feat_src -----------------------------
    #pragma unroll
    for (int mt = 0; mt < 4; mt++) {
        int m = row0 + wm + mt * 16 + (lane >> 2);
        #pragma unroll
        for (int nt = 0; nt < 4; nt++) {
            int n = n0c + wn + nt * 8 + (lane & 3) * 2;
            if (m < M) {
                float2 v = make_float2(acc[mt][nt][0], acc[mt][nt][1]);
                *reinterpret_cast<float2*>(g_feat_src + (size_t)m * HD + n) = v;
            }
            if (m + 8 < M) {
                float2 v = make_float2(acc[mt][nt][2], acc[mt][nt][3]);
                *reinterpret_cast<float2*>(g_feat_src + (size_t)(m + 8) * HD + n) = v;
            }
        }
    }

    // ---- epilogue 2: fused el/er (deterministic smem reduction) ------------
    float* s_el = reinterpret_cast<float*>(smem);           // [128][2][2]
    float* s_er = s_el + 512;                               // [128][2][2]
    const int head_local = wn >> 6;
    const int half       = (wn >> 5) & 1;

    #pragma unroll
    for (int mt = 0; mt < 4; mt++) {
        float el0 = 0.f, er0 = 0.f, el1 = 0.f, er1 = 0.f;
        #pragma unroll
        for (int nt = 0; nt < 4; nt++) {
            int c = n0c + wn + nt * 8 + (lane & 3) * 2;
            float al0 = __ldg(attn_l + c), al1 = __ldg(attn_l + c + 1);
            float ar0 = __ldg(attn_r + c), ar1 = __ldg(attn_r + c + 1);
            el0 = fmaf(acc[mt][nt][0], al0, fmaf(acc[mt][nt][1], al1, el0));
            er0 = fmaf(acc[mt][nt][0], ar0, fmaf(acc[mt][nt][1], ar1, er0));
            el1 = fmaf(acc[mt][nt][2], al0, fmaf(acc[mt][nt][3], al1, el1));
            er1 = fmaf(acc[mt][nt][2], ar0, fmaf(acc[mt][nt][3], ar1, er1));
        }
        #pragma unroll
        for (int o = 1; o < 4; o <<= 1) {
            el0 += __shfl_xor_sync(0xffffffffu, el0, o);
            er0 += __shfl_xor_sync(0xffffffffu, er0, o);
            el1 += __shfl_xor_sync(0xffffffffu, el1, o);
            er1 += __shfl_xor_sync(0xffffffffu, er1, o);
        }
        if ((lane & 3) == 0) {
            int r = wm + mt * 16 + (lane >> 2);
            s_el[(r * 2 + head_local) * 2 + half] = el0;
            s_er[(r * 2 + head_local) * 2 + half] = er0;
            s_el[((r + 8) * 2 + head_local) * 2 + half] = el1;
            s_er[((r + 8) * 2 + head_local) * 2 + half] = er1;
        }
    }
    __syncthreads();
    {
        int row = tid >> 1;
        int hl  = tid & 1;
        int gr  = row0 + row;
        if (gr < M) {
            int idx = (row * 2 + hl) * 2;
            float vl = s_el[idx] + s_el[idx + 1];
            float vr = s_er[idx] + s_er[idx + 1];
            int h = (n0c >> 6) + hl;
            g_el[gr * NH + h] = vl;
            g_er[gr * NH + h] = vr;
        }
    }
}

// ---------------- Kernel C: edge softmax + SpMM (warp per node) ------------
__global__ __launch_bounds__(256)
void agg_kernel(const int* __restrict__ row_ptr,
                const int* __restrict__ col_ind,
                float* __restrict__ out, int M)
{
    __shared__ float s_a[8][32][4];
    __shared__ int   s_src[8][32];
    const int w    = threadIdx.x >> 5;
    const int lane = threadIdx.x & 31;
    const int n    = blockIdx.x * 8 + w;
    if (n >= M) return;

    const int lo  = row_ptr[n];
    const int deg = row_ptr[n + 1] - lo;
    float* op = out + (size_t)n * HD + lane * 8;

    if (deg <= 0) {
        stg_cs4(op,     0.f, 0.f, 0.f, 0.f);
        stg_cs4(op + 4, 0.f, 0.f, 0.f, 0.f);
        return;
    }

    // ---- edge softmax (lane = edge index) ----------------------------------
    int src = 0;
    float4 e4 = make_float4(-INFINITY, -INFINITY, -INFINITY, -INFINITY);
    float4 el4 = *reinterpret_cast<const float4*>(g_el + n * NH);
    if (lane < deg) {
        src = col_ind[lo + lane];
        float4 er4 = *reinterpret_cast<const float4*>(g_er + src * NH);
        float x;
        x = er4.x + el4.x; e4.x = (x > 0.f) ? x : NEG_SLOPE * x;
        x = er4.y + el4.y; e4.y = (x > 0.f) ? x : NEG_SLOPE * x;
        x = er4.z + el4.z; e4.z = (x > 0.f) ? x : NEG_SLOPE * x;
        x = er4.w + el4.w; e4.w = (x > 0.f) ? x : NEG_SLOPE * x;
    }
    float4 mx = e4;
    #pragma unroll
    for (int o = 16; o; o >>= 1) {
        mx.x = fmaxf(mx.x, __shfl_xor_sync(0xffffffffu, mx.x, o));
        mx.y = fmaxf(mx.y, __shfl_xor_sync(0xffffffffu, mx.y, o));
        mx.z = fmaxf(mx.z, __shfl_xor_sync(0xffffffffu, mx.z, o));
        mx.w = fmaxf(mx.w, __shfl_xor_sync(0xffffffffu, mx.w, o));
    }
    float4 p = make_float4(0.f, 0.f, 0.f, 0.f);
    if (lane < deg) {
        p.x = __expf(e4.x - mx.x);
        p.y = __expf(e4.y - mx.y);
        p.z = __expf(e4.z - mx.z);
        p.w = __expf(e4.w - mx.w);
    }
    float4 s = p;
    #pragma unroll
    for (int o = 16; o; o >>= 1) {
        s.x += __shfl_xor_sync(0xffffffffu, s.x, o);
        s.y += __shfl_xor_sync(0xffffffffu, s.y, o);
        s.z += __shfl_xor_sync(0xffffffffu, s.z, o);
        s.w += __shfl_xor_sync(0xffffffffu, s.w, o);
    }
    p.x /= s.x; p.y /= s.y; p.z /= s.z; p.w /= s.w;
    if (lane < deg) {
        *reinterpret_cast<float4*>(&s_a[w][lane][0]) = p;
        s_src[w][lane] = src;
    }
    __syncwarp();

    // ---- SpMM: lane covers cols [lane*8, +8); head = lane>>3 ---------------
    const int hsel = lane >> 3;
    const float* base = g_feat_src + lane * 8;
    float acc[8];
    #pragma unroll
    for (int i = 0; i < 8; i++) acc[i] = 0.f;

    if (deg == 16) {
        #pragma unroll
        for (int j = 0; j < 16; j++) {
            int   sj = s_src[w][j];
            float a  = s_a[w][j][hsel];
            uint32_t q[8];
            ldg256_evict_last(base + (size_t)sj * HD, q);
            #pragma unroll
            for (int i = 0; i < 8; i++)
                acc[i] = fmaf(a, __uint_as_float(q[i]), acc[i]);
        }
    } else {
        #pragma unroll 4
        for (int j = 0; j < deg; j++) {
            int   sj = s_src[w][j];
            float a  = s_a[w][j][hsel];
            uint32_t q[8];
            ldg256_evict_last(base + (size_t)sj * HD, q);
            #pragma unroll
            for (int i = 0; i < 8; i++)
                acc[i] = fmaf(a, __uint_as_float(q[i]), acc[i]);
        }
    }
    stg_cs4(op,     acc[0], acc[1], acc[2], acc[3]);
    stg_cs4(op + 4, acc[4], acc[5], acc[6], acc[7]);
}

// ---------------- launch ---------------------------------------------------
extern "C" void kernel_launch(void* const* d_in, const int* in_sizes, int n_in,
                              void* d_out, int out_size)
{
    const int*   row_ptr = (const int*)  d_in[0];
    const int*   col_ind = (const int*)  d_in[1];
    const float* feat    = (const float*)d_in[2];
    const float* W       = (const float*)d_in[3];
    const float* attn_l  = (const float*)d_in[4];
    const float* attn_r  = (const float*)d_in[5];
    float* out = (float*)d_out;

    int M = in_sizes[0] - 1;   // number of nodes

    void *w_hi, *w_lo;
    cudaGetSymbolAddress(&w_hi, g_W_hi);
    cudaGetSymbolAddress(&w_lo, g_W_lo);

    // 1) bf16 hi/lo split of W only (A converts in-register inside the GEMM)
    {
        int w4 = in_sizes[3] / 4;
        convert_kernel<<<(w4 + 255) / 256, 256>>>(
            W, (__nv_bfloat16*)w_hi, (__nv_bfloat16*)w_lo, w4);
    }

    // 2) split-bf16 HMMA GEMM with fused el/er epilogue
    {
        static int smem_set = 0;
        if (!smem_set) {
            cudaFuncSetAttribute(gemm_hmma_kernel,
                                 cudaFuncAttributeMaxDynamicSharedMemorySize,
                                 2 * STAGE_BYTES);
            smem_set = 1;
        }
        dim3 grid(HD / 128, (M + 127) / 128);
        gemm_hmma_kernel<<<grid, 256, 2 * STAGE_BYTES>>>(feat, attn_l, attn_r, M);
    }

    // 3) edge softmax + aggregate (warp per node)
    {
        int blocks = (M + 7) / 8;
        agg_kernel<<<blocks, 256>>>(row_ptr, col_ind, out, M);
    }
}

// round 8
// speedup vs baseline: 3.0201x; 1.3072x over previous
#include <cuda_runtime.h>
#include <cuda_bf16.h>
#include <cuda_fp16.h>
#include <cstdint>
#include <math.h>

// Problem constants (fixed by the dataset)
#define N_NODES 100000
#define IN_F    256
#define HD      256
#define NH      4
#define DH      64
#define NEG_SLOPE 0.2f

// ---------------- scratch (device globals; no allocation allowed) ----------
__device__ __half g_feat_h[(size_t)N_NODES * HD];    // 51.2 MB (gather copy)
__device__ float g_el[N_NODES * NH];
__device__ float g_er[N_NODES * NH];
__device__ __nv_bfloat16 g_W_hi[HD * IN_F];
__device__ __nv_bfloat16 g_W_lo[HD * IN_F];

// ---------------- helpers ---------------------------------------------------
__device__ __forceinline__ uint32_t smem_u32(const void* p) {
    uint32_t a;
    asm("{ .reg .u64 t; cvta.to.shared.u64 t, %1; cvt.u32.u64 %0, t; }"
        : "=r"(a) : "l"(p));
    return a;
}

#define LDSM_X4(r, addr)                                                      \
    asm volatile("ldmatrix.sync.aligned.m8n8.x4.shared.b16 {%0,%1,%2,%3}, [%4];" \
        : "=r"((r)[0]), "=r"((r)[1]), "=r"((r)[2]), "=r"((r)[3]) : "r"(addr))

#define MMA_BF16(d, a, b0, b1)                                                \
    asm volatile("mma.sync.aligned.m16n8k16.row.col.f32.bf16.bf16.f32 "       \
        "{%0,%1,%2,%3}, {%4,%5,%6,%7}, {%8,%9}, {%0,%1,%2,%3};"               \
        : "+f"((d)[0]), "+f"((d)[1]), "+f"((d)[2]), "+f"((d)[3])              \
        : "r"((a)[0]), "r"((a)[1]), "r"((a)[2]), "r"((a)[3]),                 \
          "r"(b0), "r"(b1))

#define CP_ASYNC16(saddr, gptr, sz)                                           \
    asm volatile("cp.async.cg.shared.global [%0], [%1], 16, %2;"              \
        :: "r"(saddr), "l"(gptr), "r"(sz))

// Streaming store (evict-first) so `out` does not evict feat_h from L2
__device__ __forceinline__ void stg_cs4(float* p, float a, float b, float c, float d) {
    asm volatile("st.global.cs.v4.f32 [%0], {%1,%2,%3,%4};"
                 :: "l"(p), "f"(a), "f"(b), "f"(c), "f"(d));
}

// ---------------- Kernel A: fp32 -> bf16 hi/lo split (W only, tiny) --------
__global__ void convert_kernel(const float* __restrict__ src,
                               __nv_bfloat16* __restrict__ hi,
                               __nv_bfloat16* __restrict__ lo, int n4)
{
    int i = blockIdx.x * blockDim.x + threadIdx.x;
    if (i >= n4) return;
    float4 v = reinterpret_cast<const float4*>(src)[i];
    __nv_bfloat16 h0 = __float2bfloat16(v.x);
    __nv_bfloat16 h1 = __float2bfloat16(v.y);
    __nv_bfloat16 h2 = __float2bfloat16(v.z);
    __nv_bfloat16 h3 = __float2bfloat16(v.w);
    __nv_bfloat16 l0 = __float2bfloat16(v.x - __bfloat162float(h0));
    __nv_bfloat16 l1 = __float2bfloat16(v.y - __bfloat162float(h1));
    __nv_bfloat16 l2 = __float2bfloat16(v.z - __bfloat162float(h2));
    __nv_bfloat16 l3 = __float2bfloat16(v.w - __bfloat162float(h3));
    __nv_bfloat162* hp = reinterpret_cast<__nv_bfloat162*>(hi);
    __nv_bfloat162* lp = reinterpret_cast<__nv_bfloat162*>(lo);
    hp[2 * i]     = __halves2bfloat162(h0, h1);
    hp[2 * i + 1] = __halves2bfloat162(h2, h3);
    lp[2 * i]     = __halves2bfloat162(l0, l1);
    lp[2 * i + 1] = __halves2bfloat162(l2, l3);
}

// ---------------- Kernel B: split-bf16 HMMA GEMM + fused el/er -------------
// A loaded as fp32, converted to hi/lo bf16 in regs; output stored fp16.
#define STAGE_BYTES 40960
#define ROWB 80

__global__ __launch_bounds__(256, 2)
void gemm_hmma_kernel(const float* __restrict__ A,
                      const float* __restrict__ attn_l,
                      const float* __restrict__ attn_r, int M)
{
    extern __shared__ char smem[];
    const uint32_t sbase = smem_u32(smem);
    const int tid  = threadIdx.x;
    const int lane = tid & 31;
    const int wid  = tid >> 5;
    const int row0 = blockIdx.y * 128;
    const int n0c  = blockIdx.x * 128;
    const int wm   = (wid >> 2) * 64;
    const int wn   = (wid & 3) * 32;

    float acc[4][4][4];
    #pragma unroll
    for (int mt = 0; mt < 4; mt++)
        #pragma unroll
        for (int nt = 0; nt < 4; nt++)
            #pragma unroll
            for (int r = 0; r < 4; r++) acc[mt][nt][r] = 0.f;

    auto load_W = [&](int chunk, int stage) {
        #pragma unroll
        for (int j = 0; j < 4; j++) {
            int t    = tid + j * 256;
            int tile = t >> 9;        // 0:Wh 1:Wl
            int c    = t & 511;
            int row  = c >> 2;
            int seg  = c & 3;
            const __nv_bfloat16* gp = (tile == 0 ? g_W_hi : g_W_lo)
                + (size_t)(n0c + row) * IN_F + chunk * 32 + seg * 8;
            uint32_t sa = sbase + stage * STAGE_BYTES + 20480 + tile * 10240
                        + row * ROWB + seg * 16;
            CP_ASYNC16(sa, gp, 16);
        }
        asm volatile("cp.async.commit_group;");
    };

    float4 areg[4];
    auto ldg_A = [&](int chunk) {
        #pragma unroll
        for (int j = 0; j < 4; j++) {
            int idx = tid + j * 256;
            int row = idx >> 3;
            int seg = idx & 7;
            int gr  = row0 + row;
            areg[j] = (gr < M)
                ? *reinterpret_cast<const float4*>(
                      A + (size_t)gr * IN_F + chunk * 32 + seg * 4)
                : make_float4(0.f, 0.f, 0.f, 0.f);
        }
    };
    auto sts_A = [&](int stage) {
        #pragma unroll
        for (int j = 0; j < 4; j++) {
            int idx = tid + j * 256;
            int row = idx >> 3;
            int seg = idx & 7;
            float4 v = areg[j];
            __nv_bfloat16 h0 = __float2bfloat16(v.x);
            __nv_bfloat16 h1 = __float2bfloat16(v.y);
            __nv_bfloat16 h2 = __float2bfloat16(v.z);
            __nv_bfloat16 h3 = __float2bfloat16(v.w);
            __nv_bfloat162 hlo = __halves2bfloat162(h0, h1);
            __nv_bfloat162 hhi = __halves2bfloat162(h2, h3);
            __nv_bfloat162 llo = __halves2bfloat162(
                __float2bfloat16(v.x - __bfloat162float(h0)),
                __float2bfloat16(v.y - __bfloat162float(h1)));
            __nv_bfloat162 lhi = __halves2bfloat162(
                __float2bfloat16(v.z - __bfloat162float(h2)),
                __float2bfloat16(v.w - __bfloat162float(h3)));
            uint32_t off = stage * STAGE_BYTES + row * ROWB + seg * 8;
            char* base = smem + off;
            *reinterpret_cast<__nv_bfloat162*>(base)             = hlo;
            *reinterpret_cast<__nv_bfloat162*>(base + 4)         = hhi;
            *reinterpret_cast<__nv_bfloat162*>(base + 10240)     = llo;
            *reinterpret_cast<__nv_bfloat162*>(base + 10240 + 4) = lhi;
        }
    };

    auto compute = [&](int stage) {
        const uint32_t sb = sbase + stage * STAGE_BYTES;
        #pragma unroll
        for (int ks = 0; ks < 2; ks++) {
            const int k0 = ks * 16;
            uint32_t ah[4][4], al[4][4], bh[2][4], bl[2][4];
            #pragma unroll
            for (int mt = 0; mt < 4; mt++) {
                int r = wm + mt * 16 + (lane & 15);
                int c = k0 + ((lane >> 4) << 3);
                uint32_t off = sb + r * ROWB + c * 2;
                LDSM_X4(ah[mt], off);
                LDSM_X4(al[mt], off + 10240);
            }
            #pragma unroll
            for (int p = 0; p < 2; p++) {
                int matid = lane >> 3;
                int nr = wn + p * 16 + ((matid >> 1) << 3) + (lane & 7);
                int kc = k0 + ((matid & 1) << 3);
                uint32_t off = sb + 20480 + nr * ROWB + kc * 2;
                LDSM_X4(bh[p], off);
                LDSM_X4(bl[p], off + 10240);
            }
            #pragma unroll
            for (int mt = 0; mt < 4; mt++) {
                #pragma unroll
                for (int nt = 0; nt < 4; nt++) {
                    uint32_t b0h = bh[nt >> 1][(nt & 1) * 2];
                    uint32_t b1h = bh[nt >> 1][(nt & 1) * 2 + 1];
                    uint32_t b0l = bl[nt >> 1][(nt & 1) * 2];
                    uint32_t b1l = bl[nt >> 1][(nt & 1) * 2 + 1];
                    MMA_BF16(acc[mt][nt], ah[mt], b0h, b1h);   // hi*hi
                    MMA_BF16(acc[mt][nt], ah[mt], b0l, b1l);   // hi*lo
                    MMA_BF16(acc[mt][nt], al[mt], b0h, b1h);   // lo*hi
                }
            }
        }
    };

    ldg_A(0);
    load_W(0, 0);
    #pragma unroll 1
    for (int ch = 0; ch < 8; ch++) {
        const int s = ch & 1;
        if (ch < 7) {
            load_W(ch + 1, s ^ 1);
            asm volatile("cp.async.wait_group 1;");
        } else {
            asm volatile("cp.async.wait_group 0;");
        }
        sts_A(s);
        __syncthreads();
        if (ch < 7) ldg_A(ch + 1);
        compute(s);
        __syncthreads();
    }

    // ---- epilogue 1: fp16 stores to g_feat_h -------------------------------
    #pragma unroll
    for (int mt = 0; mt < 4; mt++) {
        int m = row0 + wm + mt * 16 + (lane >> 2);
        #pragma unroll
        for (int nt = 0; nt < 4; nt++) {
            int n = n0c + wn + nt * 8 + (lane & 3) * 2;
            if (m < M) {
                __half2 v = __floats2half2_rn(acc[mt][nt][0], acc[mt][nt][1]);
                *reinterpret_cast<__half2*>(g_feat_h + (size_t)m * HD + n) = v;
            }
            if (m + 8 < M) {
                __half2 v = __floats2half2_rn(acc[mt][nt][2], acc[mt][nt][3]);
                *reinterpret_cast<__half2*>(g_feat_h + (size_t)(m + 8) * HD + n) = v;
            }
        }
    }

    // ---- epilogue 2: fused el/er (deterministic smem reduction) ------------
    float* s_el = reinterpret_cast<float*>(smem);           // [128][2][2]
    float* s_er = s_el + 512;                               // [128][2][2]
    const int head_local = wn >> 6;
    const int half       = (wn >> 5) & 1;

    #pragma unroll
    for (int mt = 0; mt < 4; mt++) {
        float el0 = 0.f, er0 = 0.f, el1 = 0.f, er1 = 0.f;
        #pragma unroll
        for (int nt = 0; nt < 4; nt++) {
            int c = n0c + wn + nt * 8 + (lane & 3) * 2;
            float al0 = __ldg(attn_l + c), al1 = __ldg(attn_l + c + 1);
            float ar0 = __ldg(attn_r + c), ar1 = __ldg(attn_r + c + 1);
            el0 = fmaf(acc[mt][nt][0], al0, fmaf(acc[mt][nt][1], al1, el0));
            er0 = fmaf(acc[mt][nt][0], ar0, fmaf(acc[mt][nt][1], ar1, er0));
            el1 = fmaf(acc[mt][nt][2], al0, fmaf(acc[mt][nt][3], al1, el1));
            er1 = fmaf(acc[mt][nt][2], ar0, fmaf(acc[mt][nt][3], ar1, er1));
        }
        #pragma unroll
        for (int o = 1; o < 4; o <<= 1) {
            el0 += __shfl_xor_sync(0xffffffffu, el0, o);
            er0 += __shfl_xor_sync(0xffffffffu, er0, o);
            el1 += __shfl_xor_sync(0xffffffffu, el1, o);
            er1 += __shfl_xor_sync(0xffffffffu, er1, o);
        }
        if ((lane & 3) == 0) {
            int r = wm + mt * 16 + (lane >> 2);
            s_el[(r * 2 + head_local) * 2 + half] = el0;
            s_er[(r * 2 + head_local) * 2 + half] = er0;
            s_el[((r + 8) * 2 + head_local) * 2 + half] = el1;
            s_er[((r + 8) * 2 + head_local) * 2 + half] = er1;
        }
    }
    __syncthreads();
    {
        int row = tid >> 1;
        int hl  = tid & 1;
        int gr  = row0 + row;
        if (gr < M) {
            int idx = (row * 2 + hl) * 2;
            float vl = s_el[idx] + s_el[idx + 1];
            float vr = s_er[idx] + s_er[idx + 1];
            int h = (n0c >> 6) + hl;
            g_el[gr * NH + h] = vl;
            g_er[gr * NH + h] = vr;
        }
    }
}

// ---------------- Kernel C: edge softmax + SpMM (warp per node) ------------
// Lane owns 8 contiguous cols; fp16 gather = 16B per lane per edge.
__global__ __launch_bounds__(256)
void agg_kernel(const int* __restrict__ row_ptr,
                const int* __restrict__ col_ind,
                float* __restrict__ out, int M)
{
    __shared__ float s_a[8][32][4];
    __shared__ int   s_src[8][32];
    const int w    = threadIdx.x >> 5;
    const int lane = threadIdx.x & 31;
    const int n    = blockIdx.x * 8 + w;
    if (n >= M) return;

    const int lo  = row_ptr[n];
    const int deg = row_ptr[n + 1] - lo;
    float* op = out + (size_t)n * HD + lane * 8;

    if (deg <= 0) {
        stg_cs4(op,     0.f, 0.f, 0.f, 0.f);
        stg_cs4(op + 4, 0.f, 0.f, 0.f, 0.f);
        return;
    }

    // ---- edge softmax (lane = edge index) ----------------------------------
    int src = 0;
    float4 e4 = make_float4(-INFINITY, -INFINITY, -INFINITY, -INFINITY);
    float4 el4 = *reinterpret_cast<const float4*>(g_el + n * NH);
    if (lane < deg) {
        src = col_ind[lo + lane];
        float4 er4 = *reinterpret_cast<const float4*>(g_er + src * NH);
        float x;
        x = er4.x + el4.x; e4.x = (x > 0.f) ? x : NEG_SLOPE * x;
        x = er4.y + el4.y; e4.y = (x > 0.f) ? x : NEG_SLOPE * x;
        x = er4.z + el4.z; e4.z = (x > 0.f) ? x : NEG_SLOPE * x;
        x = er4.w + el4.w; e4.w = (x > 0.f) ? x : NEG_SLOPE * x;
    }
    float4 mx = e4;
    #pragma unroll
    for (int o = 16; o; o >>= 1) {
        mx.x = fmaxf(mx.x, __shfl_xor_sync(0xffffffffu, mx.x, o));
        mx.y = fmaxf(mx.y, __shfl_xor_sync(0xffffffffu, mx.y, o));
        mx.z = fmaxf(mx.z, __shfl_xor_sync(0xffffffffu, mx.z, o));
        mx.w = fmaxf(mx.w, __shfl_xor_sync(0xffffffffu, mx.w, o));
    }
    float4 p = make_float4(0.f, 0.f, 0.f, 0.f);
    if (lane < deg) {
        p.x = __expf(e4.x - mx.x);
        p.y = __expf(e4.y - mx.y);
        p.z = __expf(e4.z - mx.z);
        p.w = __expf(e4.w - mx.w);
    }
    float4 s = p;
    #pragma unroll
    for (int o = 16; o; o >>= 1) {
        s.x += __shfl_xor_sync(0xffffffffu, s.x, o);
        s.y += __shfl_xor_sync(0xffffffffu, s.y, o);
        s.z += __shfl_xor_sync(0xffffffffu, s.z, o);
        s.w += __shfl_xor_sync(0xffffffffu, s.w, o);
    }
    p.x /= s.x; p.y /= s.y; p.z /= s.z; p.w /= s.w;
    if (lane < deg) {
        *reinterpret_cast<float4*>(&s_a[w][lane][0]) = p;
        s_src[w][lane] = src;
    }
    __syncwarp();

    // ---- SpMM: lane covers cols [lane*8, +8); head = lane>>3 ---------------
    const int hsel = lane >> 3;
    const __half* base = g_feat_h + lane * 8;
    float acc[8];
    #pragma unroll
    for (int i = 0; i < 8; i++) acc[i] = 0.f;

    if (deg == 16) {
        #pragma unroll
        for (int j = 0; j < 16; j++) {
            int   sj = s_src[w][j];
            float a  = s_a[w][j][hsel];
            uint4 q = __ldg(reinterpret_cast<const uint4*>(base + (size_t)sj * HD));
            float2 f0 = __half22float2(*reinterpret_cast<__half2*>(&q.x));
            float2 f1 = __half22float2(*reinterpret_cast<__half2*>(&q.y));
            float2 f2 = __half22float2(*reinterpret_cast<__half2*>(&q.z));
            float2 f3 = __half22float2(*reinterpret_cast<__half2*>(&q.w));
            acc[0] = fmaf(a, f0.x, acc[0]);
            acc[1] = fmaf(a, f0.y, acc[1]);
            acc[2] = fmaf(a, f1.x, acc[2]);
            acc[3] = fmaf(a, f1.y, acc[3]);
            acc[4] = fmaf(a, f2.x, acc[4]);
            acc[5] = fmaf(a, f2.y, acc[5]);
            acc[6] = fmaf(a, f3.x, acc[6]);
            acc[7] = fmaf(a, f3.y, acc[7]);
        }
    } else {
        #pragma unroll 4
        for (int j = 0; j < deg; j++) {
            int   sj = s_src[w][j];
            float a  = s_a[w][j][hsel];
            uint4 q = __ldg(reinterpret_cast<const uint4*>(base + (size_t)sj * HD));
            float2 f0 = __half22float2(*reinterpret_cast<__half2*>(&q.x));
            float2 f1 = __half22float2(*reinterpret_cast<__half2*>(&q.y));
            float2 f2 = __half22float2(*reinterpret_cast<__half2*>(&q.z));
            float2 f3 = __half22float2(*reinterpret_cast<__half2*>(&q.w));
            acc[0] = fmaf(a, f0.x, acc[0]);
            acc[1] = fmaf(a, f0.y, acc[1]);
            acc[2] = fmaf(a, f1.x, acc[2]);
            acc[3] = fmaf(a, f1.y, acc[3]);
            acc[4] = fmaf(a, f2.x, acc[4]);
            acc[5] = fmaf(a, f2.y, acc[5]);
            acc[6] = fmaf(a, f3.x, acc[6]);
            acc[7] = fmaf(a, f3.y, acc[7]);
        }
    }
    stg_cs4(op,     acc[0], acc[1], acc[2], acc[3]);
    stg_cs4(op + 4, acc[4], acc[5], acc[6], acc[7]);
}

// ---------------- launch ---------------------------------------------------
extern "C" void kernel_launch(void* const* d_in, const int* in_sizes, int n_in,
                              void* d_out, int out_size)
{
    const int*   row_ptr = (const int*)  d_in[0];
    const int*   col_ind = (const int*)  d_in[1];
    const float* feat    = (const float*)d_in[2];
    const float* W       = (const float*)d_in[3];
    const float* attn_l  = (const float*)d_in[4];
    const float* attn_r  = (const float*)d_in[5];
    float* out = (float*)d_out;

    int M = in_sizes[0] - 1;   // number of nodes

    void *w_hi, *w_lo;
    cudaGetSymbolAddress(&w_hi, g_W_hi);
    cudaGetSymbolAddress(&w_lo, g_W_lo);

    // 1) bf16 hi/lo split of W only
    {
        int w4 = in_sizes[3] / 4;
        convert_kernel<<<(w4 + 255) / 256, 256>>>(
            W, (__nv_bfloat16*)w_hi, (__nv_bfloat16*)w_lo, w4);
    }

    // 2) split-bf16 HMMA GEMM with fused el/er epilogue, fp16 feat out
    {
        static int smem_set = 0;
        if (!smem_set) {
            cudaFuncSetAttribute(gemm_hmma_kernel,
                                 cudaFuncAttributeMaxDynamicSharedMemorySize,
                                 2 * STAGE_BYTES);
            smem_set = 1;
        }
        dim3 grid(HD / 128, (M + 127) / 128);
        gemm_hmma_kernel<<<grid, 256, 2 * STAGE_BYTES>>>(feat, attn_l, attn_r, M);
    }

    // 3) edge softmax + aggregate (warp per node, fp16 gather)
    {
        int blocks = (M + 7) / 8;
        agg_kernel<<<blocks, 256>>>(row_ptr, col_ind, out, M);
    }
}

// round 11
// speedup vs baseline: 3.4980x; 1.1582x over previous
#include <cuda_runtime.h>
#include <cuda_fp16.h>
#include <cstdint>
#include <math.h>

// Problem constants (fixed by the dataset)
#define N_NODES 100000
#define IN_F    256
#define HD      256
#define NH      4
#define DH      64
#define NEG_SLOPE 0.2f

// ---------------- scratch (device globals; no allocation allowed) ----------
__device__ __half g_feat_h[(size_t)N_NODES * HD];    // 51.2 MB (gather copy)
__device__ float g_el[N_NODES * NH];
__device__ float g_er[N_NODES * NH];
__device__ __half g_W_hi[HD * IN_F];
__device__ __half g_W_lo[HD * IN_F];

// ---------------- helpers ---------------------------------------------------
__device__ __forceinline__ uint32_t smem_u32(const void* p) {
    uint32_t a;
    asm("{ .reg .u64 t; cvta.to.shared.u64 t, %1; cvt.u32.u64 %0, t; }"
        : "=r"(a) : "l"(p));
    return a;
}

#define LDSM_X4(r, addr)                                                      \
    asm volatile("ldmatrix.sync.aligned.m8n8.x4.shared.b16 {%0,%1,%2,%3}, [%4];" \
        : "=r"((r)[0]), "=r"((r)[1]), "=r"((r)[2]), "=r"((r)[3]) : "r"(addr))

#define MMA_F16(d, a, b0, b1)                                                 \
    asm volatile("mma.sync.aligned.m16n8k16.row.col.f32.f16.f16.f32 "         \
        "{%0,%1,%2,%3}, {%4,%5,%6,%7}, {%8,%9}, {%0,%1,%2,%3};"               \
        : "+f"((d)[0]), "+f"((d)[1]), "+f"((d)[2]), "+f"((d)[3])              \
        : "r"((a)[0]), "r"((a)[1]), "r"((a)[2]), "r"((a)[3]),                 \
          "r"(b0), "r"(b1))

#define CP_ASYNC16(saddr, gptr, sz)                                           \
    asm volatile("cp.async.cg.shared.global [%0], [%1], 16, %2;"              \
        :: "r"(saddr), "l"(gptr), "r"(sz))

// Streaming store (evict-first) so `out` does not evict feat_h from L2
__device__ __forceinline__ void stg_cs4(float* p, float a, float b, float c, float d) {
    asm volatile("st.global.cs.v4.f32 [%0], {%1,%2,%3,%4};"
                 :: "l"(p), "f"(a), "f"(b), "f"(c), "f"(d));
}

// ---------------- Kernel A: fp32 -> fp16 hi/lo split (W only, tiny) --------
__global__ void convert_kernel(const float* __restrict__ src,
                               __half* __restrict__ hi,
                               __half* __restrict__ lo, int n4)
{
    int i = blockIdx.x * blockDim.x + threadIdx.x;
    if (i >= n4) return;
    float4 v = reinterpret_cast<const float4*>(src)[i];
    __half h0 = __float2half_rn(v.x);
    __half h1 = __float2half_rn(v.y);
    __half h2 = __float2half_rn(v.z);
    __half h3 = __float2half_rn(v.w);
    __half l0 = __float2half_rn(v.x - __half2float(h0));
    __half l1 = __float2half_rn(v.y - __half2float(h1));
    __half l2 = __float2half_rn(v.z - __half2float(h2));
    __half l3 = __float2half_rn(v.w - __half2float(h3));
    __half2* hp = reinterpret_cast<__half2*>(hi);
    __half2* lp = reinterpret_cast<__half2*>(lo);
    hp[2 * i]     = __halves2half2(h0, h1);
    hp[2 * i + 1] = __halves2half2(h2, h3);
    lp[2 * i]     = __halves2half2(l0, l1);
    lp[2 * i + 1] = __halves2half2(l2, l3);
}

// ---------------- Kernel B: fp16 2-term HMMA GEMM + fused el/er ------------
// C = A16 * (Wh + Wl)^T ; A rounded to fp16 in regs, W split fp16 hi/lo.
// smem per stage: A 10240 | Wh 10240 | Wl 10240 = 30720 B; rows 80 B padded.
#define STAGE_BYTES 30720
#define ROWB 80

__global__ __launch_bounds__(256, 2)
void gemm_hmma_kernel(const float* __restrict__ A,
                      const float* __restrict__ attn_l,
                      const float* __restrict__ attn_r, int M)
{
    extern __shared__ char smem[];
    const uint32_t sbase = smem_u32(smem);
    const int tid  = threadIdx.x;
    const int lane = tid & 31;
    const int wid  = tid >> 5;
    const int row0 = blockIdx.y * 128;
    const int n0c  = blockIdx.x * 128;
    const int wm   = (wid >> 2) * 64;
    const int wn   = (wid & 3) * 32;

    float acc[4][4][4];
    #pragma unroll
    for (int mt = 0; mt < 4; mt++)
        #pragma unroll
        for (int nt = 0; nt < 4; nt++)
            #pragma unroll
            for (int r = 0; r < 4; r++) acc[mt][nt][r] = 0.f;

    // W stage loader: Wh + Wl tiles (2 x 512 16B chunks = 1024 / 256 thr)
    auto load_W = [&](int chunk, int stage) {
        #pragma unroll
        for (int j = 0; j < 4; j++) {
            int t    = tid + j * 256;
            int tile = t >> 9;        // 0:Wh 1:Wl
            int c    = t & 511;
            int row  = c >> 2;
            int seg  = c & 3;
            const __half* gp = (tile == 0 ? g_W_hi : g_W_lo)
                + (size_t)(n0c + row) * IN_F + chunk * 32 + seg * 8;
            uint32_t sa = sbase + stage * STAGE_BYTES + 10240 + tile * 10240
                        + row * ROWB + seg * 16;
            CP_ASYNC16(sa, gp, 16);
        }
        asm volatile("cp.async.commit_group;");
    };

    float4 areg[4];
    auto ldg_A = [&](int chunk) {
        #pragma unroll
        for (int j = 0; j < 4; j++) {
            int idx = tid + j * 256;
            int row = idx >> 3;
            int seg = idx & 7;
            int gr  = row0 + row;
            areg[j] = (gr < M)
                ? *reinterpret_cast<const float4*>(
                      A + (size_t)gr * IN_F + chunk * 32 + seg * 4)
                : make_float4(0.f, 0.f, 0.f, 0.f);
        }
    };
    auto sts_A = [&](int stage) {
        #pragma unroll
        for (int j = 0; j < 4; j++) {
            int idx = tid + j * 256;
            int row = idx >> 3;
            int seg = idx & 7;
            float4 v = areg[j];
            __half2 lo2 = __floats2half2_rn(v.x, v.y);
            __half2 hi2 = __floats2half2_rn(v.z, v.w);
            char* base = smem + stage * STAGE_BYTES + row * ROWB + seg * 8;
            *reinterpret_cast<__half2*>(base)     = lo2;
            *reinterpret_cast<__half2*>(base + 4) = hi2;
        }
    };

    auto compute = [&](int stage) {
        const uint32_t sb = sbase + stage * STAGE_BYTES;
        #pragma unroll
        for (int ks = 0; ks < 2; ks++) {
            const int k0 = ks * 16;
            uint32_t af[4][4], bh[2][4], bl[2][4];
            #pragma unroll
            for (int mt = 0; mt < 4; mt++) {
                int r = wm + mt * 16 + (lane & 15);
                int c = k0 + ((lane >> 4) << 3);
                LDSM_X4(af[mt], sb + r * ROWB + c * 2);
            }
            #pragma unroll
            for (int p = 0; p < 2; p++) {
                int matid = lane >> 3;
                int nr = wn + p * 16 + ((matid >> 1) << 3) + (lane & 7);
                int kc = k0 + ((matid & 1) << 3);
                uint32_t off = sb + 10240 + nr * ROWB + kc * 2;
                LDSM_X4(bh[p], off);
                LDSM_X4(bl[p], off + 10240);
            }
            #pragma unroll
            for (int mt = 0; mt < 4; mt++) {
                #pragma unroll
                for (int nt = 0; nt < 4; nt++) {
                    uint32_t b0h = bh[nt >> 1][(nt & 1) * 2];
                    uint32_t b1h = bh[nt >> 1][(nt & 1) * 2 + 1];
                    uint32_t b0l = bl[nt >> 1][(nt & 1) * 2];
                    uint32_t b1l = bl[nt >> 1][(nt & 1) * 2 + 1];
                    MMA_F16(acc[mt][nt], af[mt], b0h, b1h);   // A * Wh
                    MMA_F16(acc[mt][nt], af[mt], b0l, b1l);   // A * Wl
                }
            }
        }
    };

    ldg_A(0);
    load_W(0, 0);
    #pragma unroll 1
    for (int ch = 0; ch < 8; ch++) {
        const int s = ch & 1;
        if (ch < 7) {
            load_W(ch + 1, s ^ 1);
            asm volatile("cp.async.wait_group 1;");
        } else {
            asm volatile("cp.async.wait_group 0;");
        }
        sts_A(s);
        __syncthreads();
        if (ch < 7) ldg_A(ch + 1);
        compute(s);
        __syncthreads();
    }

    // ---- epilogue 1: fp16 stores to g_feat_h -------------------------------
    #pragma unroll
    for (int mt = 0; mt < 4; mt++) {
        int m = row0 + wm + mt * 16 + (lane >> 2);
        #pragma unroll
        for (int nt = 0; nt < 4; nt++) {
            int n = n0c + wn + nt * 8 + (lane & 3) * 2;
            if (m < M) {
                __half2 v = __floats2half2_rn(acc[mt][nt][0], acc[mt][nt][1]);
                *reinterpret_cast<__half2*>(g_feat_h + (size_t)m * HD + n) = v;
            }
            if (m + 8 < M) {
                __half2 v = __floats2half2_rn(acc[mt][nt][2], acc[mt][nt][3]);
                *reinterpret_cast<__half2*>(g_feat_h + (size_t)(m + 8) * HD + n) = v;
            }
        }
    }

    // ---- epilogue 2: fused el/er (deterministic smem reduction) ------------
    float* s_el = reinterpret_cast<float*>(smem);           // [128][2][2]
    float* s_er = s_el + 512;                               // [128][2][2]
    const int head_local = wn >> 6;
    const int half       = (wn >> 5) & 1;

    #pragma unroll
    for (int mt = 0; mt < 4; mt++) {
        float el0 = 0.f, er0 = 0.f, el1 = 0.f, er1 = 0.f;
        #pragma unroll
        for (int nt = 0; nt < 4; nt++) {
            int c = n0c + wn + nt * 8 + (lane & 3) * 2;
            float al0 = __ldg(attn_l + c), al1 = __ldg(attn_l + c + 1);
            float ar0 = __ldg(attn_r + c), ar1 = __ldg(attn_r + c + 1);
            el0 = fmaf(acc[mt][nt][0], al0, fmaf(acc[mt][nt][1], al1, el0));
            er0 = fmaf(acc[mt][nt][0], ar0, fmaf(acc[mt][nt][1], ar1, er0));
            el1 = fmaf(acc[mt][nt][2], al0, fmaf(acc[mt][nt][3], al1, el1));
            er1 = fmaf(acc[mt][nt][2], ar0, fmaf(acc[mt][nt][3], ar1, er1));
        }
        #pragma unroll
        for (int o = 1; o < 4; o <<= 1) {
            el0 += __shfl_xor_sync(0xffffffffu, el0, o);
            er0 += __shfl_xor_sync(0xffffffffu, er0, o);
            el1 += __shfl_xor_sync(0xffffffffu, el1, o);
            er1 += __shfl_xor_sync(0xffffffffu, er1, o);
        }
        if ((lane & 3) == 0) {
            int r = wm + mt * 16 + (lane >> 2);
            s_el[(r * 2 + head_local) * 2 + half] = el0;
            s_er[(r * 2 + head_local) * 2 + half] = er0;
            s_el[((r + 8) * 2 + head_local) * 2 + half] = el1;
            s_er[((r + 8) * 2 + head_local) * 2 + half] = er1;
        }
    }
    __syncthreads();
    {
        int row = tid >> 1;
        int hl  = tid & 1;
        int gr  = row0 + row;
        if (gr < M) {
            int idx = (row * 2 + hl) * 2;
            float vl = s_el[idx] + s_el[idx + 1];
            float vr = s_er[idx] + s_er[idx + 1];
            int h = (n0c >> 6) + hl;
            g_el[gr * NH + h] = vl;
            g_er[gr * NH + h] = vr;
        }
    }
}

// ---------------- Kernel C: edge softmax + SpMM (warp per node) ------------
__global__ __launch_bounds__(256)
void agg_kernel(const int* __restrict__ row_ptr,
                const int* __restrict__ col_ind,
                float* __restrict__ out, int M)
{
    __shared__ float s_a[8][32][4];
    __shared__ int   s_src[8][32];
    const int w    = threadIdx.x >> 5;
    const int lane = threadIdx.x & 31;
    const int n    = blockIdx.x * 8 + w;
    if (n >= M) return;

    const int lo  = row_ptr[n];
    const int deg = row_ptr[n + 1] - lo;
    float* op = out + (size_t)n * HD + lane * 8;

    if (deg <= 0) {
        stg_cs4(op,     0.f, 0.f, 0.f, 0.f);
        stg_cs4(op + 4, 0.f, 0.f, 0.f, 0.f);
        return;
    }

    // ---- edge softmax (lane = edge index) ----------------------------------
    int src = 0;
    float4 e4 = make_float4(-INFINITY, -INFINITY, -INFINITY, -INFINITY);
    float4 el4 = *reinterpret_cast<const float4*>(g_el + n * NH);
    if (lane < deg) {
        src = col_ind[lo + lane];
        float4 er4 = *reinterpret_cast<const float4*>(g_er + src * NH);
        float x;
        x = er4.x + el4.x; e4.x = (x > 0.f) ? x : NEG_SLOPE * x;
        x = er4.y + el4.y; e4.y = (x > 0.f) ? x : NEG_SLOPE * x;
        x = er4.z + el4.z; e4.z = (x > 0.f) ? x : NEG_SLOPE * x;
        x = er4.w + el4.w; e4.w = (x > 0.f) ? x : NEG_SLOPE * x;
    }
    float4 mx = e4;
    #pragma unroll
    for (int o = 16; o; o >>= 1) {
        mx.x = fmaxf(mx.x, __shfl_xor_sync(0xffffffffu, mx.x, o));
        mx.y = fmaxf(mx.y, __shfl_xor_sync(0xffffffffu, mx.y, o));
        mx.z = fmaxf(mx.z, __shfl_xor_sync(0xffffffffu, mx.z, o));
        mx.w = fmaxf(mx.w, __shfl_xor_sync(0xffffffffu, mx.w, o));
    }
    float4 p = make_float4(0.f, 0.f, 0.f, 0.f);
    if (lane < deg) {
        p.x = __expf(e4.x - mx.x);
        p.y = __expf(e4.y - mx.y);
        p.z = __expf(e4.z - mx.z);
        p.w = __expf(e4.w - mx.w);
    }
    float4 s = p;
    #pragma unroll
    for (int o = 16; o; o >>= 1) {
        s.x += __shfl_xor_sync(0xffffffffu, s.x, o);
        s.y += __shfl_xor_sync(0xffffffffu, s.y, o);
        s.z += __shfl_xor_sync(0xffffffffu, s.z, o);
        s.w += __shfl_xor_sync(0xffffffffu, s.w, o);
    }
    p.x /= s.x; p.y /= s.y; p.z /= s.z; p.w /= s.w;
    if (lane < deg) {
        *reinterpret_cast<float4*>(&s_a[w][lane][0]) = p;
        s_src[w][lane] = src;
    }
    __syncwarp();

    // ---- SpMM: lane covers cols [lane*8, +8); head = lane>>3 ---------------
    const int hsel = lane >> 3;
    const __half* base = g_feat_h + lane * 8;
    float acc[8];
    #pragma unroll
    for (int i = 0; i < 8; i++) acc[i] = 0.f;

    if (deg == 16) {
        #pragma unroll
        for (int j = 0; j < 16; j++) {
            int   sj = s_src[w][j];
            float a  = s_a[w][j][hsel];
            uint4 q = __ldg(reinterpret_cast<const uint4*>(base + (size_t)sj * HD));
            float2 f0 = __half22float2(*reinterpret_cast<__half2*>(&q.x));
            float2 f1 = __half22float2(*reinterpret_cast<__half2*>(&q.y));
            float2 f2 = __half22float2(*reinterpret_cast<__half2*>(&q.z));
            float2 f3 = __half22float2(*reinterpret_cast<__half2*>(&q.w));
            acc[0] = fmaf(a, f0.x, acc[0]);
            acc[1] = fmaf(a, f0.y, acc[1]);
            acc[2] = fmaf(a, f1.x, acc[2]);
            acc[3] = fmaf(a, f1.y, acc[3]);
            acc[4] = fmaf(a, f2.x, acc[4]);
            acc[5] = fmaf(a, f2.y, acc[5]);
            acc[6] = fmaf(a, f3.x, acc[6]);
            acc[7] = fmaf(a, f3.y, acc[7]);
        }
    } else {
        #pragma unroll 4
        for (int j = 0; j < deg; j++) {
            int   sj = s_src[w][j];
            float a  = s_a[w][j][hsel];
            uint4 q = __ldg(reinterpret_cast<const uint4*>(base + (size_t)sj * HD));
            float2 f0 = __half22float2(*reinterpret_cast<__half2*>(&q.x));
            float2 f1 = __half22float2(*reinterpret_cast<__half2*>(&q.y));
            float2 f2 = __half22float2(*reinterpret_cast<__half2*>(&q.z));
            float2 f3 = __half22float2(*reinterpret_cast<__half2*>(&q.w));
            acc[0] = fmaf(a, f0.x, acc[0]);
            acc[1] = fmaf(a, f0.y, acc[1]);
            acc[2] = fmaf(a, f1.x, acc[2]);
            acc[3] = fmaf(a, f1.y, acc[3]);
            acc[4] = fmaf(a, f2.x, acc[4]);
            acc[5] = fmaf(a, f2.y, acc[5]);
            acc[6] = fmaf(a, f3.x, acc[6]);
            acc[7] = fmaf(a, f3.y, acc[7]);
        }
    }
    stg_cs4(op,     acc[0], acc[1], acc[2], acc[3]);
    stg_cs4(op + 4, acc[4], acc[5], acc[6], acc[7]);
}

// ---------------- launch ---------------------------------------------------
extern "C" void kernel_launch(void* const* d_in, const int* in_sizes, int n_in,
                              void* d_out, int out_size)
{
    const int*   row_ptr = (const int*)  d_in[0];
    const int*   col_ind = (const int*)  d_in[1];
    const float* feat    = (const float*)d_in[2];
    const float* W       = (const float*)d_in[3];
    const float* attn_l  = (const float*)d_in[4];
    const float* attn_r  = (const float*)d_in[5];
    float* out = (float*)d_out;

    int M = in_sizes[0] - 1;   // number of nodes

    void *w_hi, *w_lo;
    cudaGetSymbolAddress(&w_hi, g_W_hi);
    cudaGetSymbolAddress(&w_lo, g_W_lo);

    // 1) fp16 hi/lo split of W only
    {
        int w4 = in_sizes[3] / 4;
        convert_kernel<<<(w4 + 255) / 256, 256>>>(
            W, (__half*)w_hi, (__half*)w_lo, w4);
    }

    // 2) fp16 2-term HMMA GEMM with fused el/er epilogue, fp16 feat out
    {
        static int smem_set = 0;
        if (!smem_set) {
            cudaFuncSetAttribute(gemm_hmma_kernel,
                                 cudaFuncAttributeMaxDynamicSharedMemorySize,
                                 2 * STAGE_BYTES);
            smem_set = 1;
        }
        dim3 grid(HD / 128, (M + 127) / 128);
        gemm_hmma_kernel<<<grid, 256, 2 * STAGE_BYTES>>>(feat, attn_l, attn_r, M);
    }

    // 3) edge softmax + aggregate (warp per node, fp16 gather)
    {
        int blocks = (M + 7) / 8;
        agg_kernel<<<blocks, 256>>>(row_ptr, col_ind, out, M);
    }
}

// round 13
// speedup vs baseline: 4.0706x; 1.1637x over previous
#include <cuda_runtime.h>
#include <cuda_fp16.h>
#include <cstdint>
#include <math.h>

// Problem constants (fixed by the dataset)
#define N_NODES 100000
#define IN_F    256
#define HD      256
#define NH      4
#define DH      64
#define NEG_SLOPE 0.2f

// ---------------- scratch (device globals; no allocation allowed) ----------
__device__ __half g_feat_h[(size_t)N_NODES * HD];    // 51.2 MB (gather copy)
__device__ float g_el[N_NODES * NH];
__device__ float g_er[N_NODES * NH];
__device__ __half g_W_h[HD * IN_F];

// ---------------- helpers ---------------------------------------------------
__device__ __forceinline__ uint32_t smem_u32(const void* p) {
    uint32_t a;
    asm("{ .reg .u64 t; cvta.to.shared.u64 t, %1; cvt.u32.u64 %0, t; }"
        : "=r"(a) : "l"(p));
    return a;
}

#define LDSM_X4(r, addr)                                                      \
    asm volatile("ldmatrix.sync.aligned.m8n8.x4.shared.b16 {%0,%1,%2,%3}, [%4];" \
        : "=r"((r)[0]), "=r"((r)[1]), "=r"((r)[2]), "=r"((r)[3]) : "r"(addr))

#define MMA_F16(d, a, b0, b1)                                                 \
    asm volatile("mma.sync.aligned.m16n8k16.row.col.f32.f16.f16.f32 "         \
        "{%0,%1,%2,%3}, {%4,%5,%6,%7}, {%8,%9}, {%0,%1,%2,%3};"               \
        : "+f"((d)[0]), "+f"((d)[1]), "+f"((d)[2]), "+f"((d)[3])              \
        : "r"((a)[0]), "r"((a)[1]), "r"((a)[2]), "r"((a)[3]),                 \
          "r"(b0), "r"(b1))

#define CP_ASYNC16(saddr, gptr, sz)                                           \
    asm volatile("cp.async.cg.shared.global [%0], [%1], 16, %2;"              \
        :: "r"(saddr), "l"(gptr), "r"(sz))

// Streaming store (evict-first) so `out` does not evict feat_h from L2
__device__ __forceinline__ void stg_cs4(float* p, float a, float b, float c, float d) {
    asm volatile("st.global.cs.v4.f32 [%0], {%1,%2,%3,%4};"
                 :: "l"(p), "f"(a), "f"(b), "f"(c), "f"(d));
}

// ---------------- Kernel A: fp32 -> fp16 (W only, tiny) --------------------
__global__ void convert_kernel(const float* __restrict__ src,
                               __half* __restrict__ dst, int n4)
{
    int i = blockIdx.x * blockDim.x + threadIdx.x;
    if (i >= n4) return;
    float4 v = reinterpret_cast<const float4*>(src)[i];
    __half2* hp = reinterpret_cast<__half2*>(dst);
    hp[2 * i]     = __floats2half2_rn(v.x, v.y);
    hp[2 * i + 1] = __floats2half2_rn(v.z, v.w);
}

// ---------------- Kernel B: fp16 HMMA GEMM + fused el/er -------------------
// C = A16 * W16^T ; A rounded to fp16 in regs, W pre-converted fp16.
// smem per stage: A 10240 | W 10240 = 20480 B; rows 80 B padded.
#define STAGE_BYTES 20480
#define ROWB 80

__global__ __launch_bounds__(256, 2)
void gemm_hmma_kernel(const float* __restrict__ A,
                      const float* __restrict__ attn_l,
                      const float* __restrict__ attn_r, int M)
{
    extern __shared__ char smem[];
    const uint32_t sbase = smem_u32(smem);
    const int tid  = threadIdx.x;
    const int lane = tid & 31;
    const int wid  = tid >> 5;
    const int row0 = blockIdx.y * 128;
    const int n0c  = blockIdx.x * 128;
    const int wm   = (wid >> 2) * 64;
    const int wn   = (wid & 3) * 32;

    float acc[4][4][4];
    #pragma unroll
    for (int mt = 0; mt < 4; mt++)
        #pragma unroll
        for (int nt = 0; nt < 4; nt++)
            #pragma unroll
            for (int r = 0; r < 4; r++) acc[mt][nt][r] = 0.f;

    // W stage loader: 512 16B chunks / 256 thr = 2 each
    auto load_W = [&](int chunk, int stage) {
        #pragma unroll
        for (int j = 0; j < 2; j++) {
            int t   = tid + j * 256;
            int row = t >> 2;
            int seg = t & 3;
            const __half* gp = g_W_h
                + (size_t)(n0c + row) * IN_F + chunk * 32 + seg * 8;
            uint32_t sa = sbase + stage * STAGE_BYTES + 10240
                        + row * ROWB + seg * 16;
            CP_ASYNC16(sa, gp, 16);
        }
        asm volatile("cp.async.commit_group;");
    };

    float4 areg[4];
    auto ldg_A = [&](int chunk) {
        #pragma unroll
        for (int j = 0; j < 4; j++) {
            int idx = tid + j * 256;
            int row = idx >> 3;
            int seg = idx & 7;
            int gr  = row0 + row;
            areg[j] = (gr < M)
                ? *reinterpret_cast<const float4*>(
                      A + (size_t)gr * IN_F + chunk * 32 + seg * 4)
                : make_float4(0.f, 0.f, 0.f, 0.f);
        }
    };
    auto sts_A = [&](int stage) {
        #pragma unroll
        for (int j = 0; j < 4; j++) {
            int idx = tid + j * 256;
            int row = idx >> 3;
            int seg = idx & 7;
            float4 v = areg[j];
            __half2 lo2 = __floats2half2_rn(v.x, v.y);
            __half2 hi2 = __floats2half2_rn(v.z, v.w);
            char* base = smem + stage * STAGE_BYTES + row * ROWB + seg * 8;
            *reinterpret_cast<__half2*>(base)     = lo2;
            *reinterpret_cast<__half2*>(base + 4) = hi2;
        }
    };

    auto compute = [&](int stage) {
        const uint32_t sb = sbase + stage * STAGE_BYTES;
        #pragma unroll
        for (int ks = 0; ks < 2; ks++) {
            const int k0 = ks * 16;
            uint32_t af[4][4], bh[2][4];
            #pragma unroll
            for (int mt = 0; mt < 4; mt++) {
                int r = wm + mt * 16 + (lane & 15);
                int c = k0 + ((lane >> 4) << 3);
                LDSM_X4(af[mt], sb + r * ROWB + c * 2);
            }
            #pragma unroll
            for (int p = 0; p < 2; p++) {
                int matid = lane >> 3;
                int nr = wn + p * 16 + ((matid >> 1) << 3) + (lane & 7);
                int kc = k0 + ((matid & 1) << 3);
                LDSM_X4(bh[p], sb + 10240 + nr * ROWB + kc * 2);
            }
            #pragma unroll
            for (int mt = 0; mt < 4; mt++) {
                #pragma unroll
                for (int nt = 0; nt < 4; nt++) {
                    uint32_t b0 = bh[nt >> 1][(nt & 1) * 2];
                    uint32_t b1 = bh[nt >> 1][(nt & 1) * 2 + 1];
                    MMA_F16(acc[mt][nt], af[mt], b0, b1);
                }
            }
        }
    };

    ldg_A(0);
    load_W(0, 0);
    #pragma unroll 1
    for (int ch = 0; ch < 8; ch++) {
        const int s = ch & 1;
        if (ch < 7) {
            load_W(ch + 1, s ^ 1);
            asm volatile("cp.async.wait_group 1;");
        } else {
            asm volatile("cp.async.wait_group 0;");
        }
        sts_A(s);
        __syncthreads();
        if (ch < 7) ldg_A(ch + 1);
        compute(s);
        __syncthreads();
    }

    // ---- epilogue 1: fp16 stores to g_feat_h -------------------------------
    #pragma unroll
    for (int mt = 0; mt < 4; mt++) {
        int m = row0 + wm + mt * 16 + (lane >> 2);
        #pragma unroll
        for (int nt = 0; nt < 4; nt++) {
            int n = n0c + wn + nt * 8 + (lane & 3) * 2;
            if (m < M) {
                __half2 v = __floats2half2_rn(acc[mt][nt][0], acc[mt][nt][1]);
                *reinterpret_cast<__half2*>(g_feat_h + (size_t)m * HD + n) = v;
            }
            if (m + 8 < M) {
                __half2 v = __floats2half2_rn(acc[mt][nt][2], acc[mt][nt][3]);
                *reinterpret_cast<__half2*>(g_feat_h + (size_t)(m + 8) * HD + n) = v;
            }
        }
    }

    // ---- epilogue 2: fused el/er (deterministic smem reduction) ------------
    float* s_el = reinterpret_cast<float*>(smem);           // [128][2][2]
    float* s_er = s_el + 512;                               // [128][2][2]
    const int head_local = wn >> 6;
    const int half       = (wn >> 5) & 1;

    #pragma unroll
    for (int mt = 0; mt < 4; mt++) {
        float el0 = 0.f, er0 = 0.f, el1 = 0.f, er1 = 0.f;
        #pragma unroll
        for (int nt = 0; nt < 4; nt++) {
            int c = n0c + wn + nt * 8 + (lane & 3) * 2;
            float al0 = __ldg(attn_l + c), al1 = __ldg(attn_l + c + 1);
            float ar0 = __ldg(attn_r + c), ar1 = __ldg(attn_r + c + 1);
            el0 = fmaf(acc[mt][nt][0], al0, fmaf(acc[mt][nt][1], al1, el0));
            er0 = fmaf(acc[mt][nt][0], ar0, fmaf(acc[mt][nt][1], ar1, er0));
            el1 = fmaf(acc[mt][nt][2], al0, fmaf(acc[mt][nt][3], al1, el1));
            er1 = fmaf(acc[mt][nt][2], ar0, fmaf(acc[mt][nt][3], ar1, er1));
        }
        #pragma unroll
        for (int o = 1; o < 4; o <<= 1) {
            el0 += __shfl_xor_sync(0xffffffffu, el0, o);
            er0 += __shfl_xor_sync(0xffffffffu, er0, o);
            el1 += __shfl_xor_sync(0xffffffffu, el1, o);
            er1 += __shfl_xor_sync(0xffffffffu, er1, o);
        }
        if ((lane & 3) == 0) {
            int r = wm + mt * 16 + (lane >> 2);
            s_el[(r * 2 + head_local) * 2 + half] = el0;
            s_er[(r * 2 + head_local) * 2 + half] = er0;
            s_el[((r + 8) * 2 + head_local) * 2 + half] = el1;
            s_er[((r + 8) * 2 + head_local) * 2 + half] = er1;
        }
    }
    __syncthreads();
    {
        int row = tid >> 1;
        int hl  = tid & 1;
        int gr  = row0 + row;
        if (gr < M) {
            int idx = (row * 2 + hl) * 2;
            float vl = s_el[idx] + s_el[idx + 1];
            float vr = s_er[idx] + s_er[idx + 1];
            int h = (n0c >> 6) + hl;
            g_el[gr * NH + h] = vl;
            g_er[gr * NH + h] = vr;
        }
    }
}

// ---------------- Kernel C: edge softmax + SpMM (warp per node) ------------
__global__ __launch_bounds__(256)
void agg_kernel(const int* __restrict__ row_ptr,
                const int* __restrict__ col_ind,
                float* __restrict__ out, int M)
{
    __shared__ float s_a[8][32][4];
    __shared__ int   s_src[8][32];
    const int w    = threadIdx.x >> 5;
    const int lane = threadIdx.x & 31;
    const int n    = blockIdx.x * 8 + w;
    if (n >= M) return;

    const int lo  = row_ptr[n];
    const int deg = row_ptr[n + 1] - lo;
    float* op = out + (size_t)n * HD + lane * 8;

    if (deg <= 0) {
        stg_cs4(op,     0.f, 0.f, 0.f, 0.f);
        stg_cs4(op + 4, 0.f, 0.f, 0.f, 0.f);
        return;
    }

    // ---- edge softmax (lane = edge index) ----------------------------------
    int src = 0;
    float4 e4 = make_float4(-INFINITY, -INFINITY, -INFINITY, -INFINITY);
    float4 el4 = *reinterpret_cast<const float4*>(g_el + n * NH);
    if (lane < deg) {
        src = col_ind[lo + lane];
        float4 er4 = *reinterpret_cast<const float4*>(g_er + src * NH);
        float x;
        x = er4.x + el4.x; e4.x = (x > 0.f) ? x : NEG_SLOPE * x;
        x = er4.y + el4.y; e4.y = (x > 0.f) ? x : NEG_SLOPE * x;
        x = er4.z + el4.z; e4.z = (x > 0.f) ? x : NEG_SLOPE * x;
        x = er4.w + el4.w; e4.w = (x > 0.f) ? x : NEG_SLOPE * x;
    }
    float4 mx = e4;
    #pragma unroll
    for (int o = 16; o; o >>= 1) {
        mx.x = fmaxf(mx.x, __shfl_xor_sync(0xffffffffu, mx.x, o));
        mx.y = fmaxf(mx.y, __shfl_xor_sync(0xffffffffu, mx.y, o));
        mx.z = fmaxf(mx.z, __shfl_xor_sync(0xffffffffu, mx.z, o));
        mx.w = fmaxf(mx.w, __shfl_xor_sync(0xffffffffu, mx.w, o));
    }
    float4 p = make_float4(0.f, 0.f, 0.f, 0.f);
    if (lane < deg) {
        p.x = __expf(e4.x - mx.x);
        p.y = __expf(e4.y - mx.y);
        p.z = __expf(e4.z - mx.z);
        p.w = __expf(e4.w - mx.w);
    }
    float4 s = p;
    #pragma unroll
    for (int o = 16; o; o >>= 1) {
        s.x += __shfl_xor_sync(0xffffffffu, s.x, o);
        s.y += __shfl_xor_sync(0xffffffffu, s.y, o);
        s.z += __shfl_xor_sync(0xffffffffu, s.z, o);
        s.w += __shfl_xor_sync(0xffffffffu, s.w, o);
    }
    p.x /= s.x; p.y /= s.y; p.z /= s.z; p.w /= s.w;
    if (lane < deg) {
        *reinterpret_cast<float4*>(&s_a[w][lane][0]) = p;
        s_src[w][lane] = src;
    }
    __syncwarp();

    // ---- SpMM: lane covers cols [lane*8, +8); head = lane>>3 ---------------
    const int hsel = lane >> 3;
    const __half* base = g_feat_h + lane * 8;
    float acc[8];
    #pragma unroll
    for (int i = 0; i < 8; i++) acc[i] = 0.f;

    if (deg == 16) {
        #pragma unroll
        for (int j = 0; j < 16; j++) {
            int   sj = s_src[w][j];
            float a  = s_a[w][j][hsel];
            uint4 q = __ldg(reinterpret_cast<const uint4*>(base + (size_t)sj * HD));
            float2 f0 = __half22float2(*reinterpret_cast<__half2*>(&q.x));
            float2 f1 = __half22float2(*reinterpret_cast<__half2*>(&q.y));
            float2 f2 = __half22float2(*reinterpret_cast<__half2*>(&q.z));
            float2 f3 = __half22float2(*reinterpret_cast<__half2*>(&q.w));
            acc[0] = fmaf(a, f0.x, acc[0]);
            acc[1] = fmaf(a, f0.y, acc[1]);
            acc[2] = fmaf(a, f1.x, acc[2]);
            acc[3] = fmaf(a, f1.y, acc[3]);
            acc[4] = fmaf(a, f2.x, acc[4]);
            acc[5] = fmaf(a, f2.y, acc[5]);
            acc[6] = fmaf(a, f3.x, acc[6]);
            acc[7] = fmaf(a, f3.y, acc[7]);
        }
    } else {
        #pragma unroll 4
        for (int j = 0; j < deg; j++) {
            int   sj = s_src[w][j];
            float a  = s_a[w][j][hsel];
            uint4 q = __ldg(reinterpret_cast<const uint4*>(base + (size_t)sj * HD));
            float2 f0 = __half22float2(*reinterpret_cast<__half2*>(&q.x));
            float2 f1 = __half22float2(*reinterpret_cast<__half2*>(&q.y));
            float2 f2 = __half22float2(*reinterpret_cast<__half2*>(&q.z));
            float2 f3 = __half22float2(*reinterpret_cast<__half2*>(&q.w));
            acc[0] = fmaf(a, f0.x, acc[0]);
            acc[1] = fmaf(a, f0.y, acc[1]);
            acc[2] = fmaf(a, f1.x, acc[2]);
            acc[3] = fmaf(a, f1.y, acc[3]);
            acc[4] = fmaf(a, f2.x, acc[4]);
            acc[5] = fmaf(a, f2.y, acc[5]);
            acc[6] = fmaf(a, f3.x, acc[6]);
            acc[7] = fmaf(a, f3.y, acc[7]);
        }
    }
    stg_cs4(op,     acc[0], acc[1], acc[2], acc[3]);
    stg_cs4(op + 4, acc[4], acc[5], acc[6], acc[7]);
}

// ---------------- launch ---------------------------------------------------
extern "C" void kernel_launch(void* const* d_in, const int* in_sizes, int n_in,
                              void* d_out, int out_size)
{
    const int*   row_ptr = (const int*)  d_in[0];
    const int*   col_ind = (const int*)  d_in[1];
    const float* feat    = (const float*)d_in[2];
    const float* W       = (const float*)d_in[3];
    const float* attn_l  = (const float*)d_in[4];
    const float* attn_r  = (const float*)d_in[5];
    float* out = (float*)d_out;

    int M = in_sizes[0] - 1;   // number of nodes

    void *w_h;
    cudaGetSymbolAddress(&w_h, g_W_h);

    // 1) fp16 convert of W
    {
        int w4 = in_sizes[3] / 4;
        convert_kernel<<<(w4 + 255) / 256, 256>>>(W, (__half*)w_h, w4);
    }

    // 2) fp16 HMMA GEMM with fused el/er epilogue, fp16 feat out
    {
        static int smem_set = 0;
        if (!smem_set) {
            cudaFuncSetAttribute(gemm_hmma_kernel,
                                 cudaFuncAttributeMaxDynamicSharedMemorySize,
                                 2 * STAGE_BYTES);
            smem_set = 1;
        }
        dim3 grid(HD / 128, (M + 127) / 128);
        gemm_hmma_kernel<<<grid, 256, 2 * STAGE_BYTES>>>(feat, attn_l, attn_r, M);
    }

    // 3) edge softmax + aggregate (warp per node, fp16 gather)
    {
        int blocks = (M + 7) / 8;
        agg_kernel<<<blocks, 256>>>(row_ptr, col_ind, out, M);
    }
}